// round 11
// baseline (speedup 1.0000x reference)
#include <cuda_runtime.h>
#include <cuda_bf16.h>
#include <math.h>
#include <stdint.h>

#define BB 2
#define SS 2048
#define DD 1024
#define HH 16
#define HD 64
#define FF 4096
#define NN (BB*SS)   // 4096 tokens
#define NPERSIST 296 // 148 SMs x 2 CTAs

// ---------------- scratch (static device globals; no allocs) ----------------
__device__ float g_x1  [NN*DD];      // x + attn_out
__device__ __nv_bfloat16 g_xn_h [NN*DD], g_xn_l [NN*DD];
__device__ __nv_bfloat16 g_xn2_h[NN*DD], g_xn2_l[NN*DD];
__device__ __nv_bfloat16 g_at_h [NN*DD], g_at_l [NN*DD];   // attn out [B,S,D]
__device__ __nv_bfloat16 g_qkvb_h[3u*NN*DD], g_qkvb_l[3u*NN*DD]; // q,k,v [t][B,H,S,hd]
__device__ __nv_bfloat16 g_h_h  [(size_t)NN*FF], g_h_l[(size_t)NN*FF];
__device__ __nv_bfloat16 g_qkvt_h[3*DD*DD], g_qkvt_l[3*DD*DD]; // [3072,1024]
__device__ __nv_bfloat16 g_wot_h [DD*DD],   g_wot_l [DD*DD];
__device__ __nv_bfloat16 g_w1t_h [FF*DD],   g_w1t_l [FF*DD];
__device__ __nv_bfloat16 g_w2t_h [DD*FF],   g_w2t_l [DD*FF];
__device__ float g_bqkv[3*DD];

// ---------------- helpers ----------------
__device__ __forceinline__ uint32_t smem_u32(const void* p) {
    return (uint32_t)__cvta_generic_to_shared(p);
}
__device__ __forceinline__ void cp16(uint32_t s, const void* g) {
    asm volatile("cp.async.cg.shared.global [%0], [%1], 16;" :: "r"(s), "l"(g));
}
__device__ __forceinline__ void cp_commit() {
    asm volatile("cp.async.commit_group;" ::: "memory");
}
__device__ __forceinline__ void ldsm4(uint32_t* r, uint32_t addr) {
    asm volatile("ldmatrix.sync.aligned.m8n8.x4.shared.b16 {%0,%1,%2,%3}, [%4];"
        : "=r"(r[0]), "=r"(r[1]), "=r"(r[2]), "=r"(r[3]) : "r"(addr));
}
__device__ __forceinline__ void ldsm4t(uint32_t* r, uint32_t addr) {
    asm volatile("ldmatrix.sync.aligned.m8n8.x4.trans.shared.b16 {%0,%1,%2,%3}, [%4];"
        : "=r"(r[0]), "=r"(r[1]), "=r"(r[2]), "=r"(r[3]) : "r"(addr));
}
__device__ __forceinline__ void mma_bf16(float* d, const uint32_t* a, const uint32_t* b) {
    asm volatile("mma.sync.aligned.m16n8k16.row.col.f32.bf16.bf16.f32 "
        "{%0,%1,%2,%3}, {%4,%5,%6,%7}, {%8,%9}, {%0,%1,%2,%3};"
        : "+f"(d[0]), "+f"(d[1]), "+f"(d[2]), "+f"(d[3])
        : "r"(a[0]), "r"(a[1]), "r"(a[2]), "r"(a[3]), "r"(b[0]), "r"(b[1]));
}
__device__ __forceinline__ void split1(float x, unsigned short& h, unsigned short& l) {
    __nv_bfloat16 hb = __float2bfloat16(x);
    float hf = __bfloat162float(hb);
    __nv_bfloat16 lb = __float2bfloat16(x - hf);
    h = __bfloat16_as_ushort(hb);
    l = __bfloat16_as_ushort(lb);
}
// swizzled offset inside a 64B-wide tile: (row, 16B-chunk c in 0..3)
__device__ __forceinline__ uint32_t tile_off(int r, int c) {
    return (uint32_t)(((r >> 1) * 128) + (((((r & 1) << 2) | c) ^ ((r >> 1) & 7)) << 4));
}

// ---------------- LayerNorm with bf16 hi/lo split output ----------------
__global__ __launch_bounds__(256) void ln_split(const float* __restrict__ x,
                                                const float* __restrict__ gamma,
                                                const float* __restrict__ beta,
                                                __nv_bfloat16* __restrict__ oh,
                                                __nv_bfloat16* __restrict__ ol)
{
    int row = blockIdx.x;
    const float4* xr = reinterpret_cast<const float4*>(x + (size_t)row * DD);
    float4 v = xr[threadIdx.x];

    float s  = v.x + v.y + v.z + v.w;
    float sq = v.x*v.x + v.y*v.y + v.z*v.z + v.w*v.w;
    #pragma unroll
    for (int o = 16; o > 0; o >>= 1) {
        s  += __shfl_xor_sync(0xffffffffu, s,  o);
        sq += __shfl_xor_sync(0xffffffffu, sq, o);
    }
    __shared__ float ps[8], psq[8];
    int wid = threadIdx.x >> 5, lane = threadIdx.x & 31;
    if (lane == 0) { ps[wid] = s; psq[wid] = sq; }
    __syncthreads();
    float ts = 0.f, tsq = 0.f;
    #pragma unroll
    for (int i = 0; i < 8; i++) { ts += ps[i]; tsq += psq[i]; }

    float mu   = ts * (1.0f / DD);
    float var  = tsq * (1.0f / DD) - mu * mu;
    float rstd = rsqrtf(var + 1e-5f);

    float4 g = reinterpret_cast<const float4*>(gamma)[threadIdx.x];
    float4 b = reinterpret_cast<const float4*>(beta )[threadIdx.x];
    float o0 = (v.x - mu) * rstd * g.x + b.x;
    float o1 = (v.y - mu) * rstd * g.y + b.y;
    float o2 = (v.z - mu) * rstd * g.z + b.z;
    float o3 = (v.w - mu) * rstd * g.w + b.w;

    unsigned short h0,h1,h2,h3, l0,l1,l2,l3;
    split1(o0,h0,l0); split1(o1,h1,l1); split1(o2,h2,l2); split1(o3,h3,l3);
    uint2 hv = make_uint2((uint32_t)h0 | ((uint32_t)h1<<16), (uint32_t)h2 | ((uint32_t)h3<<16));
    uint2 lv = make_uint2((uint32_t)l0 | ((uint32_t)l1<<16), (uint32_t)l2 | ((uint32_t)l3<<16));
    reinterpret_cast<uint2*>(oh + (size_t)row*DD)[threadIdx.x] = hv;
    reinterpret_cast<uint2*>(ol + (size_t)row*DD)[threadIdx.x] = lv;
}

// ---------------- all-weights transpose + split (single launch) ----------------
__global__ __launch_bounds__(256) void wsplit_all(
    const float* __restrict__ Wq, const float* __restrict__ Wk,
    const float* __restrict__ Wv, const float* __restrict__ Wo,
    const float* __restrict__ W1, const float* __restrict__ W2,
    __nv_bfloat16* __restrict__ qkvth, __nv_bfloat16* __restrict__ qkvtl,
    __nv_bfloat16* __restrict__ woth,  __nv_bfloat16* __restrict__ wotl,
    __nv_bfloat16* __restrict__ w1th,  __nv_bfloat16* __restrict__ w1tl,
    __nv_bfloat16* __restrict__ w2th,  __nv_bfloat16* __restrict__ w2tl)
{
    int z = blockIdx.z;
    const float* W;
    __nv_bfloat16 *Bh, *Bl;
    int K, N, n0, k0;
    if (z < 4) {
        W  = (z==0) ? Wq : (z==1) ? Wk : (z==2) ? Wv : Wo;
        Bh = (z<3) ? qkvth + (size_t)z*DD*DD : woth;
        Bl = (z<3) ? qkvtl + (size_t)z*DD*DD : wotl;
        K = DD; N = DD;
        n0 = blockIdx.x * 32; k0 = blockIdx.y * 32;
    } else if (z < 8) {
        W = W1; Bh = w1th; Bl = w1tl; K = DD; N = FF;
        n0 = (z-4)*1024 + blockIdx.x * 32; k0 = blockIdx.y * 32;
    } else {
        W = W2; Bh = w2th; Bl = w2tl; K = FF; N = DD;
        n0 = blockIdx.x * 32; k0 = (z-8)*1024 + blockIdx.y * 32;
    }

    __shared__ float t[32][33];
    int tx = threadIdx.x & 31, ty = threadIdx.x >> 5;
    #pragma unroll
    for (int r = 0; r < 4; r++)
        t[ty + 8*r][tx] = W[(size_t)(k0 + ty + 8*r) * N + n0 + tx];
    __syncthreads();
    #pragma unroll
    for (int r = 0; r < 4; r++) {
        int n = ty + 8*r, k = tx;
        float x = t[k][n];
        unsigned short h, l;
        split1(x, h, l);
        size_t o = (size_t)(n0 + n) * K + k0 + k;
        Bh[o] = __ushort_as_bfloat16(h);
        Bl[o] = __ushort_as_bfloat16(l);
    }
}

// ---------------- concat q/k/v biases ----------------
__global__ void bias3(const float* a, const float* b, const float* c, float* o) {
    int i = blockIdx.x * 256 + threadIdx.x;
    o[i] = (i < DD) ? a[i] : (i < 2*DD) ? b[i - DD] : c[i - 2*DD];
}

// ---------------- split-bf16 warp-MMA GEMM: persistent CTAs, BK=32, 3-stage ----------------
#define MBK 32
#define SOFF_AHI 0
#define SOFF_ALO 8192
#define SOFF_BHI 16384
#define SOFF_BLO 24576
#define MSTAGE 32768
#define MSMEM (3*MSTAGE)

#define MODE_QKV3       1
#define MODE_RESID      2
#define MODE_RELU_SPLIT 3

__global__ __launch_bounds__(256, 2) void gemm_mma(
    const __nv_bfloat16* __restrict__ Ah, const __nv_bfloat16* __restrict__ Al,
    const __nv_bfloat16* __restrict__ Bh, const __nv_bfloat16* __restrict__ Bl,
    const float* __restrict__ bias, const float* __restrict__ resid,
    float* __restrict__ Cf, __nv_bfloat16* __restrict__ Ch, __nv_bfloat16* __restrict__ Cl,
    int M, int K, int N, int mode, int nTiles, int nx)
{
    extern __shared__ char smraw[];
    const uint32_t smbase = smem_u32(smraw);

    const int tid  = threadIdx.x;
    const int warp = tid >> 5;
    const int lane = tid & 31;
    const int warpMoff = (warp & 1) * 64;
    const int warpNoff = (warp >> 1) * 32;
    const int nk = K / MBK;

    const int g = lane >> 3, l8 = lane & 7;
    uint32_t aoff[2][4], boff[2][2];
    #pragma unroll
    for (int ks = 0; ks < 2; ks++) {
        #pragma unroll
        for (int mt = 0; mt < 4; mt++)
            aoff[ks][mt] = tile_off(warpMoff + mt*16 + (g & 1)*8 + l8, 2*ks + (g >> 1));
        #pragma unroll
        for (int p = 0; p < 2; p++)
            boff[ks][p]  = tile_off(warpNoff + p*16 + (g >> 1)*8 + l8, 2*ks + (g & 1));
    }

    const int rl = lane >> 2;
    const int cl = (lane & 3) * 2;

    // ---------------- persistent tile loop ----------------
    for (int tIdx = blockIdx.x; tIdx < nTiles; tIdx += gridDim.x) {
        const int mBase = (tIdx / nx) * 128;
        const int nBase = (tIdx % nx) * 128;

        auto load_stage = [&](int chunk, int s) {
            const int k0 = chunk * MBK;
            uint32_t sb = smbase + (uint32_t)s * MSTAGE;
            #pragma unroll
            for (int h = 0; h < 2; h++) {
                int id = tid + h * 256;
                int r = id >> 2, c = id & 3;
                uint32_t so = tile_off(r, c);
                size_t ga = ((size_t)(mBase + r) * K + k0 + c*8) * 2;
                size_t gb = ((size_t)(nBase + r) * K + k0 + c*8) * 2;
                cp16(sb + SOFF_AHI + so, (const char*)Ah + ga);
                cp16(sb + SOFF_ALO + so, (const char*)Al + ga);
                cp16(sb + SOFF_BHI + so, (const char*)Bh + gb);
                cp16(sb + SOFF_BLO + so, (const char*)Bl + gb);
            }
            cp_commit();
        };

        if (tIdx != (int)blockIdx.x)
            __syncthreads();    // all warps done with smem from previous tile

        load_stage(0, 0);
        load_stage(1, 1);

        float acc[4][4][4];
        #pragma unroll
        for (int mt = 0; mt < 4; mt++)
            #pragma unroll
            for (int nt = 0; nt < 4; nt++)
                #pragma unroll
                for (int e = 0; e < 4; e++) acc[mt][nt][e] = 0.f;

        for (int chunk = 0; chunk < nk; chunk++) {
            const int s = chunk % 3;
            if (chunk + 1 < nk) asm volatile("cp.async.wait_group 1;" ::: "memory");
            else                asm volatile("cp.async.wait_group 0;" ::: "memory");
            __syncthreads();
            if (chunk + 2 < nk) load_stage(chunk + 2, (chunk + 2) % 3);

            const uint32_t sb = smbase + (uint32_t)s * MSTAGE;
            #pragma unroll
            for (int ks = 0; ks < 2; ks++) {
                uint32_t bhi[4][2], blo[4][2];
                #pragma unroll
                for (int p = 0; p < 2; p++) {
                    ldsm4(&bhi[2*p][0], sb + SOFF_BHI + boff[ks][p]);
                    ldsm4(&blo[2*p][0], sb + SOFF_BLO + boff[ks][p]);
                }
                #pragma unroll
                for (int mt = 0; mt < 4; mt++) {
                    uint32_t ahi[4], alo[4];
                    ldsm4(ahi, sb + SOFF_AHI + aoff[ks][mt]);
                    ldsm4(alo, sb + SOFF_ALO + aoff[ks][mt]);
                    #pragma unroll
                    for (int nt = 0; nt < 4; nt++) {
                        mma_bf16(acc[mt][nt], ahi, bhi[nt]);
                        mma_bf16(acc[mt][nt], ahi, blo[nt]);
                        mma_bf16(acc[mt][nt], alo, bhi[nt]);
                    }
                }
            }
        }

        // ---------------- epilogue ----------------
        #pragma unroll
        for (int mt = 0; mt < 4; mt++) {
            #pragma unroll
            for (int nt = 0; nt < 4; nt++) {
                int gr0 = mBase + warpMoff + mt*16 + rl;
                int gc  = nBase + warpNoff + nt*8 + cl;
                float b0 = __ldg(&bias[gc]);
                float b1 = __ldg(&bias[gc + 1]);
                float v00 = acc[mt][nt][0] + b0, v01 = acc[mt][nt][1] + b1;
                float v10 = acc[mt][nt][2] + b0, v11 = acc[mt][nt][3] + b1;

                if (mode == MODE_QKV3) {
                    int t = gc >> 10;
                    int within = gc & 1023;
                    int h = within >> 6, jj = within & 63;
                    int p = jj >> 1;
                    float inv = expf(-0.28782313663f * (float)p);   // 10000^(-p/32)
                    #pragma unroll
                    for (int rr = 0; rr < 2; rr++) {
                        int row = gr0 + rr*8;
                        int b = row >> 11, sI = row & 2047;
                        float w0 = rr ? v10 : v00;
                        float w1 = rr ? v11 : v01;
                        if (t < 2) {
                            float sn, cs;
                            sincosf((float)sI * inv, &sn, &cs);
                            float r0 = w0 * cs - w1 * sn;
                            float r1 = w0 * sn + w1 * cs;
                            if (t == 0) { r0 *= 0.125f; r1 *= 0.125f; }
                            w0 = r0; w1 = r1;
                        }
                        unsigned short h0,l0,h1,l1;
                        split1(w0, h0, l0);
                        split1(w1, h1, l1);
                        size_t ob = (size_t)t * NN * DD +
                                    ((size_t)((b*HH + h)*SS + sI)) * HD + jj;
                        reinterpret_cast<uint32_t*>(Ch)[ob >> 1] = (uint32_t)h0 | ((uint32_t)h1 << 16);
                        reinterpret_cast<uint32_t*>(Cl)[ob >> 1] = (uint32_t)l0 | ((uint32_t)l1 << 16);
                    }
                } else if (mode == MODE_RESID) {
                    #pragma unroll
                    for (int rr = 0; rr < 2; rr++) {
                        int row = gr0 + rr*8;
                        size_t ob = (size_t)row * N + gc;
                        float2 rv = *reinterpret_cast<const float2*>(resid + ob);
                        float2 o = rr ? make_float2(v10 + rv.x, v11 + rv.y)
                                      : make_float2(v00 + rv.x, v01 + rv.y);
                        *reinterpret_cast<float2*>(Cf + ob) = o;
                    }
                } else { // MODE_RELU_SPLIT
                    #pragma unroll
                    for (int rr = 0; rr < 2; rr++) {
                        int row = gr0 + rr*8;
                        size_t ob = (size_t)row * N + gc;
                        float w0 = fmaxf(rr ? v10 : v00, 0.f);
                        float w1 = fmaxf(rr ? v11 : v01, 0.f);
                        unsigned short h0,l0,h1,l1;
                        split1(w0, h0, l0);
                        split1(w1, h1, l1);
                        reinterpret_cast<uint32_t*>(Ch)[ob >> 1] = (uint32_t)h0 | ((uint32_t)h1 << 16);
                        reinterpret_cast<uint32_t*>(Cl)[ob >> 1] = (uint32_t)l0 | ((uint32_t)l1 << 16);
                    }
                }
            }
        }
    }
}

// ---------------- split-bf16 MMA flash attention (V row-major + ldmatrix.trans) ----------------
#define AT_SQH   0
#define AT_SQL   16384
#define AT_STAGE 32768
#define AT_SSZ   32768
#define AT_KH    0
#define AT_KL    8192
#define AT_VH    16384
#define AT_VL    24576
#define ATTN_SMEM (32768 + 2*32768)

__global__ __launch_bounds__(256, 2) void attn_mma(
    const __nv_bfloat16* __restrict__ Qh, const __nv_bfloat16* __restrict__ Ql,
    const __nv_bfloat16* __restrict__ Kh, const __nv_bfloat16* __restrict__ Kl,
    const __nv_bfloat16* __restrict__ Vh, const __nv_bfloat16* __restrict__ Vl,
    __nv_bfloat16* __restrict__ Oh, __nv_bfloat16* __restrict__ Ol)
{
    extern __shared__ char smraw[];
    const uint32_t sm = smem_u32(smraw);
    const int tid = threadIdx.x, warp = tid >> 5, lane = tid & 31;
    const int bh = blockIdx.y;
    const int q0 = blockIdx.x * 128;
    const int g = lane >> 3, l8 = lane & 7;
    const int rl = lane >> 2, cl = (lane & 3) * 2;

    // load Q tiles (hi/lo), part of first commit group
    #pragma unroll
    for (int t = 0; t < 8; t++) {
        int buf = t >> 2;                    // 0=hi,1=lo
        int w = (t & 3) * 256 + tid;         // 0..1023
        int r = w >> 3, c = w & 7;
        uint32_t off = (buf ? AT_SQL : AT_SQH) + (c >> 2) * 8192 + tile_off(r, c & 3);
        const char* gp = (const char*)(buf ? Ql : Qh) +
                         ((size_t)((size_t)bh * SS + q0 + r) * HD + c * 8) * 2;
        cp16(sm + off, gp);
    }

    auto load_kv = [&](int kb, int s) {
        uint32_t sb = sm + AT_STAGE + (uint32_t)s * AT_SSZ;
        #pragma unroll
        for (int t = 0; t < 8; t++) {
            int buf = t >> 1;                // 0=Kh 1=Kl 2=Vh 3=Vl
            int w = (t & 1) * 256 + tid;     // 0..511
            int r = w >> 3, c = w & 7;
            uint32_t off = (uint32_t)buf * 8192 + (c >> 2) * 4096 + tile_off(r, c & 3);
            const __nv_bfloat16* src = (buf == 0) ? Kh : (buf == 1) ? Kl : (buf == 2) ? Vh : Vl;
            const char* gp = (const char*)src + ((size_t)((size_t)bh * SS + kb + r) * HD + c * 8) * 2;
            cp16(sb + off, gp);
        }
        cp_commit();
    };

    load_kv(0, 0);
    load_kv(64, 1);

    float m0 = -1e30f, m1 = -1e30f, l0 = 0.f, l1 = 0.f;
    float acc[8][4];
    #pragma unroll
    for (int nt = 0; nt < 8; nt++)
        #pragma unroll
        for (int e = 0; e < 4; e++) acc[nt][e] = 0.f;

    const int NT = SS / 64;
    for (int it = 0; it < NT; it++) {
        if (it + 1 < NT) asm volatile("cp.async.wait_group 1;" ::: "memory");
        else             asm volatile("cp.async.wait_group 0;" ::: "memory");
        __syncthreads();
        const uint32_t sb = sm + AT_STAGE + (uint32_t)(it & 1) * AT_SSZ;

        // ---- S = Q K^T (split 3-product) ----
        float sacc[8][4];
        #pragma unroll
        for (int nt = 0; nt < 8; nt++)
            #pragma unroll
            for (int e = 0; e < 4; e++) sacc[nt][e] = 0.f;

        #pragma unroll
        for (int ks = 0; ks < 4; ks++) {
            uint32_t qoff = (uint32_t)((ks >> 1) * 8192) +
                            tile_off(warp*16 + (g & 1)*8 + l8, 2*(ks & 1) + (g >> 1));
            uint32_t qh4[4], ql4[4];
            ldsm4(qh4, sm + AT_SQH + qoff);
            ldsm4(ql4, sm + AT_SQL + qoff);
            uint32_t kh4[4][4], kl4[4][4];
            #pragma unroll
            for (int p = 0; p < 4; p++) {
                uint32_t ko = (uint32_t)((ks >> 1) * 4096) +
                              tile_off(p*16 + (g >> 1)*8 + l8, 2*(ks & 1) + (g & 1));
                ldsm4(kh4[p], sb + AT_KH + ko);
                ldsm4(kl4[p], sb + AT_KL + ko);
            }
            #pragma unroll
            for (int nt = 0; nt < 8; nt++) {
                const uint32_t* bhk = &kh4[nt >> 1][(nt & 1) * 2];
                const uint32_t* blk = &kl4[nt >> 1][(nt & 1) * 2];
                mma_bf16(sacc[nt], qh4, bhk);
                mma_bf16(sacc[nt], qh4, blk);
                mma_bf16(sacc[nt], ql4, bhk);
            }
        }

        // ---- online softmax ----
        float mx0 = -1e30f, mx1 = -1e30f;
        #pragma unroll
        for (int nt = 0; nt < 8; nt++) {
            mx0 = fmaxf(mx0, fmaxf(sacc[nt][0], sacc[nt][1]));
            mx1 = fmaxf(mx1, fmaxf(sacc[nt][2], sacc[nt][3]));
        }
        mx0 = fmaxf(mx0, __shfl_xor_sync(0xffffffffu, mx0, 1));
        mx0 = fmaxf(mx0, __shfl_xor_sync(0xffffffffu, mx0, 2));
        mx1 = fmaxf(mx1, __shfl_xor_sync(0xffffffffu, mx1, 1));
        mx1 = fmaxf(mx1, __shfl_xor_sync(0xffffffffu, mx1, 2));

        float mn0 = fmaxf(m0, mx0), mn1 = fmaxf(m1, mx1);
        float a0 = __expf(m0 - mn0), a1 = __expf(m1 - mn1);
        float rs0 = 0.f, rs1 = 0.f;
        #pragma unroll
        for (int nt = 0; nt < 8; nt++) {
            sacc[nt][0] = __expf(sacc[nt][0] - mn0);
            sacc[nt][1] = __expf(sacc[nt][1] - mn0);
            sacc[nt][2] = __expf(sacc[nt][2] - mn1);
            sacc[nt][3] = __expf(sacc[nt][3] - mn1);
            rs0 += sacc[nt][0] + sacc[nt][1];
            rs1 += sacc[nt][2] + sacc[nt][3];
        }
        rs0 += __shfl_xor_sync(0xffffffffu, rs0, 1);
        rs0 += __shfl_xor_sync(0xffffffffu, rs0, 2);
        rs1 += __shfl_xor_sync(0xffffffffu, rs1, 1);
        rs1 += __shfl_xor_sync(0xffffffffu, rs1, 2);
        l0 = l0 * a0 + rs0;  m0 = mn0;
        l1 = l1 * a1 + rs1;  m1 = mn1;
        #pragma unroll
        for (int nt = 0; nt < 8; nt++) {
            acc[nt][0] *= a0; acc[nt][1] *= a0;
            acc[nt][2] *= a1; acc[nt][3] *= a1;
        }

        // ---- O += P V (split 3-product); V row-major, trans ldmatrix ----
        #pragma unroll
        for (int ks = 0; ks < 4; ks++) {
            uint32_t aH[4], aL[4];
            #pragma unroll
            for (int half = 0; half < 2; half++) {
                int nt = 2*ks + half;
                unsigned short h0,l0s,h1,l1s,h2,l2s,h3,l3s;
                split1(sacc[nt][0], h0, l0s);
                split1(sacc[nt][1], h1, l1s);
                split1(sacc[nt][2], h2, l2s);
                split1(sacc[nt][3], h3, l3s);
                aH[half*2 + 0] = (uint32_t)h0  | ((uint32_t)h1  << 16);
                aH[half*2 + 1] = (uint32_t)h2  | ((uint32_t)h3  << 16);
                aL[half*2 + 0] = (uint32_t)l0s | ((uint32_t)l1s << 16);
                aL[half*2 + 1] = (uint32_t)l2s | ((uint32_t)l3s << 16);
            }
            uint32_t vh4[4][4], vl4[4][4];
            int vrow = 16*ks + (g & 1)*8 + l8;
            #pragma unroll
            for (int p = 0; p < 4; p++) {
                int c = p*2 + (g >> 1);            // 16B d-chunk 0..7
                uint32_t vo = (uint32_t)((c >> 2) * 4096) + tile_off(vrow, c & 3);
                ldsm4t(vh4[p], sb + AT_VH + vo);
                ldsm4t(vl4[p], sb + AT_VL + vo);
            }
            #pragma unroll
            for (int nt = 0; nt < 8; nt++) {
                const uint32_t* bhv = &vh4[nt >> 1][(nt & 1) * 2];
                const uint32_t* blv = &vl4[nt >> 1][(nt & 1) * 2];
                mma_bf16(acc[nt], aH, bhv);
                mma_bf16(acc[nt], aL, bhv);
                mma_bf16(acc[nt], aH, blv);
            }
        }

        __syncthreads();
        if (it + 2 < NT) load_kv((it + 2) * 64, it & 1);
    }

    // ---- epilogue: normalize, split to bf16 hi/lo, write [B,S,D] ----
    float i0 = 1.f / l0, i1 = 1.f / l1;
    int b = bh >> 4, h = bh & 15;
    int s0r = q0 + warp * 16 + rl;
    #pragma unroll
    for (int nt = 0; nt < 8; nt++) {
        int col = h * 64 + nt * 8 + cl;
        {
            float w0 = acc[nt][0] * i0, w1 = acc[nt][1] * i0;
            unsigned short h0,lo0,h1,lo1;
            split1(w0, h0, lo0); split1(w1, h1, lo1);
            size_t ob = (size_t)(b * SS + s0r) * DD + col;
            reinterpret_cast<uint32_t*>(Oh)[ob >> 1] = (uint32_t)h0  | ((uint32_t)h1  << 16);
            reinterpret_cast<uint32_t*>(Ol)[ob >> 1] = (uint32_t)lo0 | ((uint32_t)lo1 << 16);
        }
        {
            float w0 = acc[nt][2] * i1, w1 = acc[nt][3] * i1;
            unsigned short h0,lo0,h1,lo1;
            split1(w0, h0, lo0); split1(w1, h1, lo1);
            size_t ob = (size_t)(b * SS + s0r + 8) * DD + col;
            reinterpret_cast<uint32_t*>(Oh)[ob >> 1] = (uint32_t)h0  | ((uint32_t)h1  << 16);
            reinterpret_cast<uint32_t*>(Ol)[ob >> 1] = (uint32_t)lo0 | ((uint32_t)lo1 << 16);
        }
    }
}

// ---------------- host launch ----------------
extern "C" void kernel_launch(void* const* d_in, const int* in_sizes, int n_in,
                              void* d_out, int out_size)
{
    const float* x     = (const float*)d_in[0];
    const float* Wq    = (const float*)d_in[1];
    const float* bq    = (const float*)d_in[2];
    const float* Wk    = (const float*)d_in[3];
    const float* bk    = (const float*)d_in[4];
    const float* Wv    = (const float*)d_in[5];
    const float* bv    = (const float*)d_in[6];
    const float* Wo    = (const float*)d_in[7];
    const float* bo    = (const float*)d_in[8];
    const float* W1    = (const float*)d_in[9];
    const float* b1    = (const float*)d_in[10];
    const float* W2    = (const float*)d_in[11];
    const float* b2    = (const float*)d_in[12];
    const float* g1    = (const float*)d_in[13];
    const float* beta1 = (const float*)d_in[14];
    const float* g2    = (const float*)d_in[15];
    const float* beta2 = (const float*)d_in[16];
    float* out = (float*)d_out;

    float *x1, *bqkv;
    __nv_bfloat16 *xnh, *xnl, *xn2h, *xn2l, *ath, *atl, *hh, *hl;
    __nv_bfloat16 *qkvbh, *qkvbl;
    __nv_bfloat16 *qkvth, *qkvtl, *woth, *wotl, *w1th, *w1tl, *w2th, *w2tl;
    cudaGetSymbolAddress((void**)&x1,    g_x1);
    cudaGetSymbolAddress((void**)&bqkv,  g_bqkv);
    cudaGetSymbolAddress((void**)&xnh,   g_xn_h);
    cudaGetSymbolAddress((void**)&xnl,   g_xn_l);
    cudaGetSymbolAddress((void**)&xn2h,  g_xn2_h);
    cudaGetSymbolAddress((void**)&xn2l,  g_xn2_l);
    cudaGetSymbolAddress((void**)&ath,   g_at_h);
    cudaGetSymbolAddress((void**)&atl,   g_at_l);
    cudaGetSymbolAddress((void**)&hh,    g_h_h);
    cudaGetSymbolAddress((void**)&hl,    g_h_l);
    cudaGetSymbolAddress((void**)&qkvbh, g_qkvb_h);
    cudaGetSymbolAddress((void**)&qkvbl, g_qkvb_l);
    cudaGetSymbolAddress((void**)&qkvth, g_qkvt_h);
    cudaGetSymbolAddress((void**)&qkvtl, g_qkvt_l);
    cudaGetSymbolAddress((void**)&woth,  g_wot_h);
    cudaGetSymbolAddress((void**)&wotl,  g_wot_l);
    cudaGetSymbolAddress((void**)&w1th,  g_w1t_h);
    cudaGetSymbolAddress((void**)&w1tl,  g_w1t_l);
    cudaGetSymbolAddress((void**)&w2th,  g_w2t_h);
    cudaGetSymbolAddress((void**)&w2tl,  g_w2t_l);

    cudaFuncSetAttribute(gemm_mma, cudaFuncAttributeMaxDynamicSharedMemorySize, MSMEM);
    cudaFuncSetAttribute(attn_mma, cudaFuncAttributeMaxDynamicSharedMemorySize, ATTN_SMEM);

    // 1: all weight transposes + splits in one launch
    wsplit_all<<<dim3(32, 32, 12), 256>>>(Wq, Wk, Wv, Wo, W1, W2,
                                          qkvth, qkvtl, woth, wotl,
                                          w1th, w1tl, w2th, w2tl);
    // 2
    bias3<<<3*DD/256, 256>>>(bq, bk, bv, bqkv);
    // 3: LN1 -> split
    ln_split<<<NN, 256>>>(x, g1, beta1, xnh, xnl);

    // 4: fused QKV projection + bias + RoPE + split (persistent: 768 tiles)
    gemm_mma<<<NPERSIST, 256, MSMEM>>>(
        xnh, xnl, qkvth, qkvtl, bqkv, nullptr, nullptr, qkvbh, qkvbl,
        NN, DD, 3*DD, MODE_QKV3, 768, 24);

    __nv_bfloat16* qh = qkvbh;
    __nv_bfloat16* ql = qkvbl;
    __nv_bfloat16* kh = qkvbh + (size_t)NN*DD;
    __nv_bfloat16* kl = qkvbl + (size_t)NN*DD;
    __nv_bfloat16* vh = qkvbh + 2*(size_t)NN*DD;
    __nv_bfloat16* vl = qkvbl + 2*(size_t)NN*DD;

    // 5: MMA flash attention -> bf16 hi/lo attn output [B,S,D]
    attn_mma<<<dim3(SS/128, BB*HH), 256, ATTN_SMEM>>>(qh, ql, kh, kl, vh, vl, ath, atl);

    // 6: x1 = x + attn @ Wo + bo   (256 tiles < 296 -> plain)
    gemm_mma<<<256, 256, MSMEM>>>(
        ath, atl, woth, wotl, bo, x, x1, nullptr, nullptr,
        NN, DD, DD, MODE_RESID, 256, 8);

    // 7: LN2 -> split
    ln_split<<<NN, 256>>>(x1, g2, beta2, xn2h, xn2l);

    // 8: FFN up: relu + split epilogue (persistent: 1024 tiles)
    gemm_mma<<<NPERSIST, 256, MSMEM>>>(
        xn2h, xn2l, w1th, w1tl, b1, nullptr, nullptr, hh, hl,
        NN, DD, FF, MODE_RELU_SPLIT, 1024, 32);

    // 9: FFN down + residual -> out (256 tiles)
    gemm_mma<<<256, 256, MSMEM>>>(
        hh, hl, w2th, w2tl, b2, x1, out, nullptr, nullptr,
        NN, FF, DD, MODE_RESID, 256, 8);
}

// round 12
// speedup vs baseline: 1.0150x; 1.0150x over previous
#include <cuda_runtime.h>
#include <cuda_bf16.h>
#include <math.h>
#include <stdint.h>

#define BB 2
#define SS 2048
#define DD 1024
#define HH 16
#define HD 64
#define FF 4096
#define NN (BB*SS)   // 4096 tokens

// ---------------- scratch (static device globals; no allocs) ----------------
__device__ float g_x1  [NN*DD];      // x + attn_out
__device__ __nv_bfloat16 g_xn_h [NN*DD], g_xn_l [NN*DD];
__device__ __nv_bfloat16 g_xn2_h[NN*DD], g_xn2_l[NN*DD];
__device__ __nv_bfloat16 g_at_h [NN*DD], g_at_l [NN*DD];   // attn out [B,S,D]
__device__ __nv_bfloat16 g_qkvb_h[3u*NN*DD], g_qkvb_l[3u*NN*DD]; // q,k,v [t][B,H,S,hd]
__device__ __nv_bfloat16 g_h_h  [(size_t)NN*FF], g_h_l[(size_t)NN*FF];
__device__ __nv_bfloat16 g_qkvt_h[3*DD*DD], g_qkvt_l[3*DD*DD]; // [3072,1024]
__device__ __nv_bfloat16 g_wot_h [DD*DD],   g_wot_l [DD*DD];
__device__ __nv_bfloat16 g_w1t_h [FF*DD],   g_w1t_l [FF*DD];
__device__ __nv_bfloat16 g_w2t_h [DD*FF],   g_w2t_l [DD*FF];
__device__ float g_bqkv[3*DD];

// ---------------- helpers ----------------
__device__ __forceinline__ uint32_t smem_u32(const void* p) {
    return (uint32_t)__cvta_generic_to_shared(p);
}
__device__ __forceinline__ void cp16(uint32_t s, const void* g) {
    asm volatile("cp.async.cg.shared.global [%0], [%1], 16;" :: "r"(s), "l"(g));
}
__device__ __forceinline__ void cp_commit() {
    asm volatile("cp.async.commit_group;" ::: "memory");
}
__device__ __forceinline__ void ldsm4(uint32_t* r, uint32_t addr) {
    asm volatile("ldmatrix.sync.aligned.m8n8.x4.shared.b16 {%0,%1,%2,%3}, [%4];"
        : "=r"(r[0]), "=r"(r[1]), "=r"(r[2]), "=r"(r[3]) : "r"(addr));
}
__device__ __forceinline__ void ldsm4t(uint32_t* r, uint32_t addr) {
    asm volatile("ldmatrix.sync.aligned.m8n8.x4.trans.shared.b16 {%0,%1,%2,%3}, [%4];"
        : "=r"(r[0]), "=r"(r[1]), "=r"(r[2]), "=r"(r[3]) : "r"(addr));
}
__device__ __forceinline__ void mma_bf16(float* d, const uint32_t* a, const uint32_t* b) {
    asm volatile("mma.sync.aligned.m16n8k16.row.col.f32.bf16.bf16.f32 "
        "{%0,%1,%2,%3}, {%4,%5,%6,%7}, {%8,%9}, {%0,%1,%2,%3};"
        : "+f"(d[0]), "+f"(d[1]), "+f"(d[2]), "+f"(d[3])
        : "r"(a[0]), "r"(a[1]), "r"(a[2]), "r"(a[3]), "r"(b[0]), "r"(b[1]));
}
__device__ __forceinline__ void split1(float x, unsigned short& h, unsigned short& l) {
    __nv_bfloat16 hb = __float2bfloat16(x);
    float hf = __bfloat162float(hb);
    __nv_bfloat16 lb = __float2bfloat16(x - hf);
    h = __bfloat16_as_ushort(hb);
    l = __bfloat16_as_ushort(lb);
}
// swizzled offset inside a 64B-wide tile: (row, 16B-chunk c in 0..3)
__device__ __forceinline__ uint32_t tile_off(int r, int c) {
    return (uint32_t)(((r >> 1) * 128) + (((((r & 1) << 2) | c) ^ ((r >> 1) & 7)) << 4));
}

// ---------------- LayerNorm with bf16 hi/lo split output ----------------
__global__ __launch_bounds__(256) void ln_split(const float* __restrict__ x,
                                                const float* __restrict__ gamma,
                                                const float* __restrict__ beta,
                                                __nv_bfloat16* __restrict__ oh,
                                                __nv_bfloat16* __restrict__ ol)
{
    int row = blockIdx.x;
    const float4* xr = reinterpret_cast<const float4*>(x + (size_t)row * DD);
    float4 v = xr[threadIdx.x];

    float s  = v.x + v.y + v.z + v.w;
    float sq = v.x*v.x + v.y*v.y + v.z*v.z + v.w*v.w;
    #pragma unroll
    for (int o = 16; o > 0; o >>= 1) {
        s  += __shfl_xor_sync(0xffffffffu, s,  o);
        sq += __shfl_xor_sync(0xffffffffu, sq, o);
    }
    __shared__ float ps[8], psq[8];
    int wid = threadIdx.x >> 5, lane = threadIdx.x & 31;
    if (lane == 0) { ps[wid] = s; psq[wid] = sq; }
    __syncthreads();
    float ts = 0.f, tsq = 0.f;
    #pragma unroll
    for (int i = 0; i < 8; i++) { ts += ps[i]; tsq += psq[i]; }

    float mu   = ts * (1.0f / DD);
    float var  = tsq * (1.0f / DD) - mu * mu;
    float rstd = rsqrtf(var + 1e-5f);

    float4 g = reinterpret_cast<const float4*>(gamma)[threadIdx.x];
    float4 b = reinterpret_cast<const float4*>(beta )[threadIdx.x];
    float o0 = (v.x - mu) * rstd * g.x + b.x;
    float o1 = (v.y - mu) * rstd * g.y + b.y;
    float o2 = (v.z - mu) * rstd * g.z + b.z;
    float o3 = (v.w - mu) * rstd * g.w + b.w;

    unsigned short h0,h1,h2,h3, l0,l1,l2,l3;
    split1(o0,h0,l0); split1(o1,h1,l1); split1(o2,h2,l2); split1(o3,h3,l3);
    uint2 hv = make_uint2((uint32_t)h0 | ((uint32_t)h1<<16), (uint32_t)h2 | ((uint32_t)h3<<16));
    uint2 lv = make_uint2((uint32_t)l0 | ((uint32_t)l1<<16), (uint32_t)l2 | ((uint32_t)l3<<16));
    reinterpret_cast<uint2*>(oh + (size_t)row*DD)[threadIdx.x] = hv;
    reinterpret_cast<uint2*>(ol + (size_t)row*DD)[threadIdx.x] = lv;
}

// ---------------- all-weights transpose + split (single launch) ----------------
__global__ __launch_bounds__(256) void wsplit_all(
    const float* __restrict__ Wq, const float* __restrict__ Wk,
    const float* __restrict__ Wv, const float* __restrict__ Wo,
    const float* __restrict__ W1, const float* __restrict__ W2,
    __nv_bfloat16* __restrict__ qkvth, __nv_bfloat16* __restrict__ qkvtl,
    __nv_bfloat16* __restrict__ woth,  __nv_bfloat16* __restrict__ wotl,
    __nv_bfloat16* __restrict__ w1th,  __nv_bfloat16* __restrict__ w1tl,
    __nv_bfloat16* __restrict__ w2th,  __nv_bfloat16* __restrict__ w2tl)
{
    int z = blockIdx.z;
    const float* W;
    __nv_bfloat16 *Bh, *Bl;
    int K, N, n0, k0;
    if (z < 4) {
        W  = (z==0) ? Wq : (z==1) ? Wk : (z==2) ? Wv : Wo;
        Bh = (z<3) ? qkvth + (size_t)z*DD*DD : woth;
        Bl = (z<3) ? qkvtl + (size_t)z*DD*DD : wotl;
        K = DD; N = DD;
        n0 = blockIdx.x * 32; k0 = blockIdx.y * 32;
    } else if (z < 8) {
        W = W1; Bh = w1th; Bl = w1tl; K = DD; N = FF;
        n0 = (z-4)*1024 + blockIdx.x * 32; k0 = blockIdx.y * 32;
    } else {
        W = W2; Bh = w2th; Bl = w2tl; K = FF; N = DD;
        n0 = blockIdx.x * 32; k0 = (z-8)*1024 + blockIdx.y * 32;
    }

    __shared__ float t[32][33];
    int tx = threadIdx.x & 31, ty = threadIdx.x >> 5;
    #pragma unroll
    for (int r = 0; r < 4; r++)
        t[ty + 8*r][tx] = W[(size_t)(k0 + ty + 8*r) * N + n0 + tx];
    __syncthreads();
    #pragma unroll
    for (int r = 0; r < 4; r++) {
        int n = ty + 8*r, k = tx;
        float x = t[k][n];
        unsigned short h, l;
        split1(x, h, l);
        size_t o = (size_t)(n0 + n) * K + k0 + k;
        Bh[o] = __ushort_as_bfloat16(h);
        Bl[o] = __ushort_as_bfloat16(l);
    }
}

// ---------------- concat q/k/v biases ----------------
__global__ void bias3(const float* a, const float* b, const float* c, float* o) {
    int i = blockIdx.x * 256 + threadIdx.x;
    o[i] = (i < DD) ? a[i] : (i < 2*DD) ? b[i - DD] : c[i - 2*DD];
}

// ---------------- split-bf16 warp-MMA GEMM: BK=32, 3-stage, 1 barrier/chunk ----------------
#define MBK 32
#define SOFF_AHI 0
#define SOFF_ALO 8192
#define SOFF_BHI 16384
#define SOFF_BLO 24576
#define MSTAGE 32768
#define MSMEM (3*MSTAGE)

#define MODE_QKV3       1
#define MODE_RESID      2
#define MODE_RELU_SPLIT 3

__global__ __launch_bounds__(256, 2) void gemm_mma(
    const __nv_bfloat16* __restrict__ Ah, const __nv_bfloat16* __restrict__ Al,
    const __nv_bfloat16* __restrict__ Bh, const __nv_bfloat16* __restrict__ Bl,
    const float* __restrict__ bias, const float* __restrict__ resid,
    float* __restrict__ Cf, __nv_bfloat16* __restrict__ Ch, __nv_bfloat16* __restrict__ Cl,
    int M, int K, int N, int mode)
{
    extern __shared__ char smraw[];
    const uint32_t smbase = smem_u32(smraw);

    const int tid  = threadIdx.x;
    const int warp = tid >> 5;
    const int lane = tid & 31;
    const int warpMoff = (warp & 1) * 64;
    const int warpNoff = (warp >> 1) * 32;
    const int mBase = blockIdx.y * 128;
    const int nBase = blockIdx.x * 128;
    const int nk = K / MBK;

    const int g = lane >> 3, l8 = lane & 7;
    uint32_t aoff[2][4], boff[2][2];
    #pragma unroll
    for (int ks = 0; ks < 2; ks++) {
        #pragma unroll
        for (int mt = 0; mt < 4; mt++)
            aoff[ks][mt] = tile_off(warpMoff + mt*16 + (g & 1)*8 + l8, 2*ks + (g >> 1));
        #pragma unroll
        for (int p = 0; p < 2; p++)
            boff[ks][p]  = tile_off(warpNoff + p*16 + (g >> 1)*8 + l8, 2*ks + (g & 1));
    }

    auto load_stage = [&](int chunk, int s) {
        const int k0 = chunk * MBK;
        uint32_t sb = smbase + (uint32_t)s * MSTAGE;
        #pragma unroll
        for (int h = 0; h < 2; h++) {
            int id = tid + h * 256;
            int r = id >> 2, c = id & 3;
            uint32_t so = tile_off(r, c);
            size_t ga = ((size_t)(mBase + r) * K + k0 + c*8) * 2;
            size_t gb = ((size_t)(nBase + r) * K + k0 + c*8) * 2;
            cp16(sb + SOFF_AHI + so, (const char*)Ah + ga);
            cp16(sb + SOFF_ALO + so, (const char*)Al + ga);
            cp16(sb + SOFF_BHI + so, (const char*)Bh + gb);
            cp16(sb + SOFF_BLO + so, (const char*)Bl + gb);
        }
        cp_commit();
    };

    // 2-deep prefetch into a 3-stage ring
    load_stage(0, 0);
    load_stage(1, 1);

    float acc[4][4][4];
    #pragma unroll
    for (int mt = 0; mt < 4; mt++)
        #pragma unroll
        for (int nt = 0; nt < 4; nt++)
            #pragma unroll
            for (int e = 0; e < 4; e++) acc[mt][nt][e] = 0.f;

    for (int chunk = 0; chunk < nk; chunk++) {
        const int s = chunk % 3;
        if (chunk + 1 < nk) asm volatile("cp.async.wait_group 1;" ::: "memory");
        else                asm volatile("cp.async.wait_group 0;" ::: "memory");
        __syncthreads();
        // stage (chunk+2)%3 == (chunk-1)%3 was drained by this barrier — reload it now,
        // overlapping the copies with this chunk's ldsm/MMA stream.
        if (chunk + 2 < nk) load_stage(chunk + 2, (chunk + 2) % 3);

        const uint32_t sb = smbase + (uint32_t)s * MSTAGE;
        #pragma unroll
        for (int ks = 0; ks < 2; ks++) {
            // B fragments first (shared across all m-tiles)
            uint32_t bhi[4][2], blo[4][2];
            #pragma unroll
            for (int p = 0; p < 2; p++) {
                ldsm4(&bhi[2*p][0], sb + SOFF_BHI + boff[ks][p]);
                ldsm4(&blo[2*p][0], sb + SOFF_BLO + boff[ks][p]);
            }
            // per m-tile: load A hi/lo, issue its 12 MMAs immediately (low live-reg)
            #pragma unroll
            for (int mt = 0; mt < 4; mt++) {
                uint32_t ahi[4], alo[4];
                ldsm4(ahi, sb + SOFF_AHI + aoff[ks][mt]);
                ldsm4(alo, sb + SOFF_ALO + aoff[ks][mt]);
                #pragma unroll
                for (int nt = 0; nt < 4; nt++) {
                    mma_bf16(acc[mt][nt], ahi, bhi[nt]);
                    mma_bf16(acc[mt][nt], ahi, blo[nt]);
                    mma_bf16(acc[mt][nt], alo, bhi[nt]);
                }
            }
        }
        // no trailing barrier: the next iteration's top barrier covers stage reuse
    }

    // ---------------- epilogue ----------------
    const int rl = lane >> 2;
    const int cl = (lane & 3) * 2;

    #pragma unroll
    for (int mt = 0; mt < 4; mt++) {
        #pragma unroll
        for (int nt = 0; nt < 4; nt++) {
            int gr0 = mBase + warpMoff + mt*16 + rl;
            int gc  = nBase + warpNoff + nt*8 + cl;
            float b0 = __ldg(&bias[gc]);
            float b1 = __ldg(&bias[gc + 1]);
            float v00 = acc[mt][nt][0] + b0, v01 = acc[mt][nt][1] + b1;
            float v10 = acc[mt][nt][2] + b0, v11 = acc[mt][nt][3] + b1;

            if (mode == MODE_QKV3) {
                int t = gc >> 10;
                int within = gc & 1023;
                int h = within >> 6, jj = within & 63;
                int p = jj >> 1;
                float inv = expf(-0.28782313663f * (float)p);   // 10000^(-p/32)
                #pragma unroll
                for (int rr = 0; rr < 2; rr++) {
                    int row = gr0 + rr*8;
                    int b = row >> 11, sI = row & 2047;
                    float w0 = rr ? v10 : v00;
                    float w1 = rr ? v11 : v01;
                    if (t < 2) {
                        float sn, cs;
                        sincosf((float)sI * inv, &sn, &cs);
                        float r0 = w0 * cs - w1 * sn;
                        float r1 = w0 * sn + w1 * cs;
                        if (t == 0) { r0 *= 0.125f; r1 *= 0.125f; }
                        w0 = r0; w1 = r1;
                    }
                    unsigned short h0,l0,h1,l1;
                    split1(w0, h0, l0);
                    split1(w1, h1, l1);
                    size_t ob = (size_t)t * NN * DD +
                                ((size_t)((b*HH + h)*SS + sI)) * HD + jj;
                    reinterpret_cast<uint32_t*>(Ch)[ob >> 1] = (uint32_t)h0 | ((uint32_t)h1 << 16);
                    reinterpret_cast<uint32_t*>(Cl)[ob >> 1] = (uint32_t)l0 | ((uint32_t)l1 << 16);
                }
            } else if (mode == MODE_RESID) {
                #pragma unroll
                for (int rr = 0; rr < 2; rr++) {
                    int row = gr0 + rr*8;
                    size_t ob = (size_t)row * N + gc;
                    float2 rv = *reinterpret_cast<const float2*>(resid + ob);
                    float2 o = rr ? make_float2(v10 + rv.x, v11 + rv.y)
                                  : make_float2(v00 + rv.x, v01 + rv.y);
                    *reinterpret_cast<float2*>(Cf + ob) = o;
                }
            } else { // MODE_RELU_SPLIT
                #pragma unroll
                for (int rr = 0; rr < 2; rr++) {
                    int row = gr0 + rr*8;
                    size_t ob = (size_t)row * N + gc;
                    float w0 = fmaxf(rr ? v10 : v00, 0.f);
                    float w1 = fmaxf(rr ? v11 : v01, 0.f);
                    unsigned short h0,l0,h1,l1;
                    split1(w0, h0, l0);
                    split1(w1, h1, l1);
                    reinterpret_cast<uint32_t*>(Ch)[ob >> 1] = (uint32_t)h0 | ((uint32_t)h1 << 16);
                    reinterpret_cast<uint32_t*>(Cl)[ob >> 1] = (uint32_t)l0 | ((uint32_t)l1 << 16);
                }
            }
        }
    }
}

// ---------------- split-bf16 MMA flash attention (Q frags hoisted to registers) ----------------
#define AT_SQH   0
#define AT_SQL   16384
#define AT_STAGE 32768
#define AT_SSZ   32768
#define AT_KH    0
#define AT_KL    8192
#define AT_VH    16384
#define AT_VL    24576
#define ATTN_SMEM (32768 + 2*32768)

__global__ __launch_bounds__(256, 2) void attn_mma(
    const __nv_bfloat16* __restrict__ Qh, const __nv_bfloat16* __restrict__ Ql,
    const __nv_bfloat16* __restrict__ Kh, const __nv_bfloat16* __restrict__ Kl,
    const __nv_bfloat16* __restrict__ Vh, const __nv_bfloat16* __restrict__ Vl,
    __nv_bfloat16* __restrict__ Oh, __nv_bfloat16* __restrict__ Ol)
{
    extern __shared__ char smraw[];
    const uint32_t sm = smem_u32(smraw);
    const int tid = threadIdx.x, warp = tid >> 5, lane = tid & 31;
    const int bh = blockIdx.y;
    const int q0 = blockIdx.x * 128;
    const int g = lane >> 3, l8 = lane & 7;
    const int rl = lane >> 2, cl = (lane & 3) * 2;

    // load Q tiles (hi/lo), part of first commit group
    #pragma unroll
    for (int t = 0; t < 8; t++) {
        int buf = t >> 2;                    // 0=hi,1=lo
        int w = (t & 3) * 256 + tid;         // 0..1023
        int r = w >> 3, c = w & 7;
        uint32_t off = (buf ? AT_SQL : AT_SQH) + (c >> 2) * 8192 + tile_off(r, c & 3);
        const char* gp = (const char*)(buf ? Ql : Qh) +
                         ((size_t)((size_t)bh * SS + q0 + r) * HD + c * 8) * 2;
        cp16(sm + off, gp);
    }

    auto load_kv = [&](int kb, int s) {
        uint32_t sb = sm + AT_STAGE + (uint32_t)s * AT_SSZ;
        #pragma unroll
        for (int t = 0; t < 8; t++) {
            int buf = t >> 1;                // 0=Kh 1=Kl 2=Vh 3=Vl
            int w = (t & 1) * 256 + tid;     // 0..511
            int r = w >> 3, c = w & 7;
            uint32_t off = (uint32_t)buf * 8192 + (c >> 2) * 4096 + tile_off(r, c & 3);
            const __nv_bfloat16* src = (buf == 0) ? Kh : (buf == 1) ? Kl : (buf == 2) ? Vh : Vl;
            const char* gp = (const char*)src + ((size_t)((size_t)bh * SS + kb + r) * HD + c * 8) * 2;
            cp16(sb + off, gp);
        }
        cp_commit();
    };

    load_kv(0, 0);
    load_kv(64, 1);

    float m0 = -1e30f, m1 = -1e30f, l0 = 0.f, l1 = 0.f;
    float acc[8][4];
    #pragma unroll
    for (int nt = 0; nt < 8; nt++)
        #pragma unroll
        for (int e = 0; e < 4; e++) acc[nt][e] = 0.f;

    // Q fragments resident in registers (loaded once at it==0)
    uint32_t qhf[4][4], qlf[4][4];

    const int NT = SS / 64;
    for (int it = 0; it < NT; it++) {
        if (it + 1 < NT) asm volatile("cp.async.wait_group 1;" ::: "memory");
        else             asm volatile("cp.async.wait_group 0;" ::: "memory");
        __syncthreads();
        const uint32_t sb = sm + AT_STAGE + (uint32_t)(it & 1) * AT_SSZ;

        if (it == 0) {
            #pragma unroll
            for (int ks = 0; ks < 4; ks++) {
                uint32_t qoff = (uint32_t)((ks >> 1) * 8192) +
                                tile_off(warp*16 + (g & 1)*8 + l8, 2*(ks & 1) + (g >> 1));
                ldsm4(qhf[ks], sm + AT_SQH + qoff);
                ldsm4(qlf[ks], sm + AT_SQL + qoff);
            }
        }

        // ---- S = Q K^T (split 3-product); K loaded per-p (low transient regs) ----
        float sacc[8][4];
        #pragma unroll
        for (int nt = 0; nt < 8; nt++)
            #pragma unroll
            for (int e = 0; e < 4; e++) sacc[nt][e] = 0.f;

        #pragma unroll
        for (int ks = 0; ks < 4; ks++) {
            #pragma unroll
            for (int p = 0; p < 4; p++) {
                uint32_t kh4[4], kl4[4];
                uint32_t ko = (uint32_t)((ks >> 1) * 4096) +
                              tile_off(p*16 + (g >> 1)*8 + l8, 2*(ks & 1) + (g & 1));
                ldsm4(kh4, sb + AT_KH + ko);
                ldsm4(kl4, sb + AT_KL + ko);
                #pragma unroll
                for (int half = 0; half < 2; half++) {
                    int nt = 2*p + half;
                    const uint32_t* bhk = &kh4[half * 2];
                    const uint32_t* blk = &kl4[half * 2];
                    mma_bf16(sacc[nt], qhf[ks], bhk);
                    mma_bf16(sacc[nt], qhf[ks], blk);
                    mma_bf16(sacc[nt], qlf[ks], bhk);
                }
            }
        }

        // ---- online softmax ----
        float mx0 = -1e30f, mx1 = -1e30f;
        #pragma unroll
        for (int nt = 0; nt < 8; nt++) {
            mx0 = fmaxf(mx0, fmaxf(sacc[nt][0], sacc[nt][1]));
            mx1 = fmaxf(mx1, fmaxf(sacc[nt][2], sacc[nt][3]));
        }
        mx0 = fmaxf(mx0, __shfl_xor_sync(0xffffffffu, mx0, 1));
        mx0 = fmaxf(mx0, __shfl_xor_sync(0xffffffffu, mx0, 2));
        mx1 = fmaxf(mx1, __shfl_xor_sync(0xffffffffu, mx1, 1));
        mx1 = fmaxf(mx1, __shfl_xor_sync(0xffffffffu, mx1, 2));

        float mn0 = fmaxf(m0, mx0), mn1 = fmaxf(m1, mx1);
        float a0 = __expf(m0 - mn0), a1 = __expf(m1 - mn1);
        float rs0 = 0.f, rs1 = 0.f;
        #pragma unroll
        for (int nt = 0; nt < 8; nt++) {
            sacc[nt][0] = __expf(sacc[nt][0] - mn0);
            sacc[nt][1] = __expf(sacc[nt][1] - mn0);
            sacc[nt][2] = __expf(sacc[nt][2] - mn1);
            sacc[nt][3] = __expf(sacc[nt][3] - mn1);
            rs0 += sacc[nt][0] + sacc[nt][1];
            rs1 += sacc[nt][2] + sacc[nt][3];
        }
        rs0 += __shfl_xor_sync(0xffffffffu, rs0, 1);
        rs0 += __shfl_xor_sync(0xffffffffu, rs0, 2);
        rs1 += __shfl_xor_sync(0xffffffffu, rs1, 1);
        rs1 += __shfl_xor_sync(0xffffffffu, rs1, 2);
        l0 = l0 * a0 + rs0;  m0 = mn0;
        l1 = l1 * a1 + rs1;  m1 = mn1;
        #pragma unroll
        for (int nt = 0; nt < 8; nt++) {
            acc[nt][0] *= a0; acc[nt][1] *= a0;
            acc[nt][2] *= a1; acc[nt][3] *= a1;
        }

        // ---- O += P V (split 3-product); V row-major, trans ldmatrix, per-p ----
        #pragma unroll
        for (int ks = 0; ks < 4; ks++) {
            uint32_t aH[4], aL[4];
            #pragma unroll
            for (int half = 0; half < 2; half++) {
                int nt = 2*ks + half;
                unsigned short h0,l0s,h1,l1s,h2,l2s,h3,l3s;
                split1(sacc[nt][0], h0, l0s);
                split1(sacc[nt][1], h1, l1s);
                split1(sacc[nt][2], h2, l2s);
                split1(sacc[nt][3], h3, l3s);
                aH[half*2 + 0] = (uint32_t)h0  | ((uint32_t)h1  << 16);
                aH[half*2 + 1] = (uint32_t)h2  | ((uint32_t)h3  << 16);
                aL[half*2 + 0] = (uint32_t)l0s | ((uint32_t)l1s << 16);
                aL[half*2 + 1] = (uint32_t)l2s | ((uint32_t)l3s << 16);
            }
            int vrow = 16*ks + (g & 1)*8 + l8;
            #pragma unroll
            for (int p = 0; p < 4; p++) {
                uint32_t vh4[4], vl4[4];
                int c = p*2 + (g >> 1);            // 16B d-chunk 0..7
                uint32_t vo = (uint32_t)((c >> 2) * 4096) + tile_off(vrow, c & 3);
                ldsm4t(vh4, sb + AT_VH + vo);
                ldsm4t(vl4, sb + AT_VL + vo);
                #pragma unroll
                for (int half = 0; half < 2; half++) {
                    int nt = 2*p + half;
                    const uint32_t* bhv = &vh4[half * 2];
                    const uint32_t* blv = &vl4[half * 2];
                    mma_bf16(acc[nt], aH, bhv);
                    mma_bf16(acc[nt], aL, bhv);
                    mma_bf16(acc[nt], aH, blv);
                }
            }
        }

        __syncthreads();
        if (it + 2 < NT) load_kv((it + 2) * 64, it & 1);
    }

    // ---- epilogue: normalize, split to bf16 hi/lo, write [B,S,D] ----
    float i0 = 1.f / l0, i1 = 1.f / l1;
    int b = bh >> 4, h = bh & 15;
    int s0r = q0 + warp * 16 + rl;
    #pragma unroll
    for (int nt = 0; nt < 8; nt++) {
        int col = h * 64 + nt * 8 + cl;
        {
            float w0 = acc[nt][0] * i0, w1 = acc[nt][1] * i0;
            unsigned short h0,lo0,h1,lo1;
            split1(w0, h0, lo0); split1(w1, h1, lo1);
            size_t ob = (size_t)(b * SS + s0r) * DD + col;
            reinterpret_cast<uint32_t*>(Oh)[ob >> 1] = (uint32_t)h0  | ((uint32_t)h1  << 16);
            reinterpret_cast<uint32_t*>(Ol)[ob >> 1] = (uint32_t)lo0 | ((uint32_t)lo1 << 16);
        }
        {
            float w0 = acc[nt][2] * i1, w1 = acc[nt][3] * i1;
            unsigned short h0,lo0,h1,lo1;
            split1(w0, h0, lo0); split1(w1, h1, lo1);
            size_t ob = (size_t)(b * SS + s0r + 8) * DD + col;
            reinterpret_cast<uint32_t*>(Oh)[ob >> 1] = (uint32_t)h0  | ((uint32_t)h1  << 16);
            reinterpret_cast<uint32_t*>(Ol)[ob >> 1] = (uint32_t)lo0 | ((uint32_t)lo1 << 16);
        }
    }
}

// ---------------- host launch ----------------
extern "C" void kernel_launch(void* const* d_in, const int* in_sizes, int n_in,
                              void* d_out, int out_size)
{
    const float* x     = (const float*)d_in[0];
    const float* Wq    = (const float*)d_in[1];
    const float* bq    = (const float*)d_in[2];
    const float* Wk    = (const float*)d_in[3];
    const float* bk    = (const float*)d_in[4];
    const float* Wv    = (const float*)d_in[5];
    const float* bv    = (const float*)d_in[6];
    const float* Wo    = (const float*)d_in[7];
    const float* bo    = (const float*)d_in[8];
    const float* W1    = (const float*)d_in[9];
    const float* b1    = (const float*)d_in[10];
    const float* W2    = (const float*)d_in[11];
    const float* b2    = (const float*)d_in[12];
    const float* g1    = (const float*)d_in[13];
    const float* beta1 = (const float*)d_in[14];
    const float* g2    = (const float*)d_in[15];
    const float* beta2 = (const float*)d_in[16];
    float* out = (float*)d_out;

    float *x1, *bqkv;
    __nv_bfloat16 *xnh, *xnl, *xn2h, *xn2l, *ath, *atl, *hh, *hl;
    __nv_bfloat16 *qkvbh, *qkvbl;
    __nv_bfloat16 *qkvth, *qkvtl, *woth, *wotl, *w1th, *w1tl, *w2th, *w2tl;
    cudaGetSymbolAddress((void**)&x1,    g_x1);
    cudaGetSymbolAddress((void**)&bqkv,  g_bqkv);
    cudaGetSymbolAddress((void**)&xnh,   g_xn_h);
    cudaGetSymbolAddress((void**)&xnl,   g_xn_l);
    cudaGetSymbolAddress((void**)&xn2h,  g_xn2_h);
    cudaGetSymbolAddress((void**)&xn2l,  g_xn2_l);
    cudaGetSymbolAddress((void**)&ath,   g_at_h);
    cudaGetSymbolAddress((void**)&atl,   g_at_l);
    cudaGetSymbolAddress((void**)&hh,    g_h_h);
    cudaGetSymbolAddress((void**)&hl,    g_h_l);
    cudaGetSymbolAddress((void**)&qkvbh, g_qkvb_h);
    cudaGetSymbolAddress((void**)&qkvbl, g_qkvb_l);
    cudaGetSymbolAddress((void**)&qkvth, g_qkvt_h);
    cudaGetSymbolAddress((void**)&qkvtl, g_qkvt_l);
    cudaGetSymbolAddress((void**)&woth,  g_wot_h);
    cudaGetSymbolAddress((void**)&wotl,  g_wot_l);
    cudaGetSymbolAddress((void**)&w1th,  g_w1t_h);
    cudaGetSymbolAddress((void**)&w1tl,  g_w1t_l);
    cudaGetSymbolAddress((void**)&w2th,  g_w2t_h);
    cudaGetSymbolAddress((void**)&w2tl,  g_w2t_l);

    cudaFuncSetAttribute(gemm_mma, cudaFuncAttributeMaxDynamicSharedMemorySize, MSMEM);
    cudaFuncSetAttribute(attn_mma, cudaFuncAttributeMaxDynamicSharedMemorySize, ATTN_SMEM);

    // 1: all weight transposes + splits in one launch
    wsplit_all<<<dim3(32, 32, 12), 256>>>(Wq, Wk, Wv, Wo, W1, W2,
                                          qkvth, qkvtl, woth, wotl,
                                          w1th, w1tl, w2th, w2tl);
    // 2
    bias3<<<3*DD/256, 256>>>(bq, bk, bv, bqkv);
    // 3: LN1 -> split
    ln_split<<<NN, 256>>>(x, g1, beta1, xnh, xnl);

    // 4: fused QKV projection + bias + RoPE + split (q,k,v bf16 hi/lo)
    gemm_mma<<<dim3(3*DD/128, NN/128), 256, MSMEM>>>(
        xnh, xnl, qkvth, qkvtl, bqkv, nullptr, nullptr, qkvbh, qkvbl,
        NN, DD, 3*DD, MODE_QKV3);

    __nv_bfloat16* qh = qkvbh;
    __nv_bfloat16* ql = qkvbl;
    __nv_bfloat16* kh = qkvbh + (size_t)NN*DD;
    __nv_bfloat16* kl = qkvbl + (size_t)NN*DD;
    __nv_bfloat16* vh = qkvbh + 2*(size_t)NN*DD;
    __nv_bfloat16* vl = qkvbl + 2*(size_t)NN*DD;

    // 5: MMA flash attention -> bf16 hi/lo attn output [B,S,D]
    attn_mma<<<dim3(SS/128, BB*HH), 256, ATTN_SMEM>>>(qh, ql, kh, kl, vh, vl, ath, atl);

    // 6: x1 = x + attn @ Wo + bo
    gemm_mma<<<dim3(DD/128, NN/128), 256, MSMEM>>>(
        ath, atl, woth, wotl, bo, x, x1, nullptr, nullptr,
        NN, DD, DD, MODE_RESID);

    // 7: LN2 -> split
    ln_split<<<NN, 256>>>(x1, g2, beta2, xn2h, xn2l);

    // 8: FFN up: relu + split epilogue
    gemm_mma<<<dim3(FF/128, NN/128), 256, MSMEM>>>(
        xn2h, xn2l, w1th, w1tl, b1, nullptr, nullptr, hh, hl,
        NN, DD, FF, MODE_RELU_SPLIT);

    // 9: FFN down + residual -> out
    gemm_mma<<<dim3(DD/128, NN/128), 256, MSMEM>>>(
        hh, hl, w2th, w2tl, b2, x1, out, nullptr, nullptr,
        NN, FF, DD, MODE_RESID);
}

// round 13
// speedup vs baseline: 1.2705x; 1.2517x over previous
#include <cuda_runtime.h>
#include <cuda_bf16.h>
#include <cuda_fp16.h>
#include <math.h>
#include <stdint.h>

#define BB 2
#define SS 2048
#define DD 1024
#define HH 16
#define HD 64
#define FF 4096
#define NN (BB*SS)   // 4096 tokens

// ---------------- scratch (static device globals; no allocs) ----------------
__device__ float g_x1  [NN*DD];      // x + attn_out
__device__ __half g_xn_h [NN*DD], g_xn_l [NN*DD];        // LN1 out, fp16 hi/lo
__device__ __half g_xn2_h[NN*DD], g_xn2_l[NN*DD];        // LN2 out
__device__ __half g_at_h [NN*DD], g_at_l [NN*DD];        // attn out [B,S,D] fp16 hi/lo
__device__ __nv_bfloat16 g_qkvb_h[3u*NN*DD], g_qkvb_l[3u*NN*DD]; // q,k,v bf16 (attention)
__device__ __half g_h_h  [(size_t)NN*FF], g_h_l[(size_t)NN*FF];  // FFN hidden fp16 hi/lo
__device__ __half g_qkvt [3*DD*DD];  // weights fp16 single [3072,1024]
__device__ __half g_wot  [DD*DD];
__device__ __half g_w1t  [FF*DD];
__device__ __half g_w2t  [DD*FF];
__device__ float g_bqkv[3*DD];

// ---------------- helpers ----------------
__device__ __forceinline__ uint32_t smem_u32(const void* p) {
    return (uint32_t)__cvta_generic_to_shared(p);
}
__device__ __forceinline__ void cp16(uint32_t s, const void* g) {
    asm volatile("cp.async.cg.shared.global [%0], [%1], 16;" :: "r"(s), "l"(g));
}
__device__ __forceinline__ void cp_commit() {
    asm volatile("cp.async.commit_group;" ::: "memory");
}
__device__ __forceinline__ void ldsm4(uint32_t* r, uint32_t addr) {
    asm volatile("ldmatrix.sync.aligned.m8n8.x4.shared.b16 {%0,%1,%2,%3}, [%4];"
        : "=r"(r[0]), "=r"(r[1]), "=r"(r[2]), "=r"(r[3]) : "r"(addr));
}
__device__ __forceinline__ void ldsm4t(uint32_t* r, uint32_t addr) {
    asm volatile("ldmatrix.sync.aligned.m8n8.x4.trans.shared.b16 {%0,%1,%2,%3}, [%4];"
        : "=r"(r[0]), "=r"(r[1]), "=r"(r[2]), "=r"(r[3]) : "r"(addr));
}
__device__ __forceinline__ void mma_bf16(float* d, const uint32_t* a, const uint32_t* b) {
    asm volatile("mma.sync.aligned.m16n8k16.row.col.f32.bf16.bf16.f32 "
        "{%0,%1,%2,%3}, {%4,%5,%6,%7}, {%8,%9}, {%0,%1,%2,%3};"
        : "+f"(d[0]), "+f"(d[1]), "+f"(d[2]), "+f"(d[3])
        : "r"(a[0]), "r"(a[1]), "r"(a[2]), "r"(a[3]), "r"(b[0]), "r"(b[1]));
}
__device__ __forceinline__ void mma_f16(float* d, const uint32_t* a, const uint32_t* b) {
    asm volatile("mma.sync.aligned.m16n8k16.row.col.f32.f16.f16.f32 "
        "{%0,%1,%2,%3}, {%4,%5,%6,%7}, {%8,%9}, {%0,%1,%2,%3};"
        : "+f"(d[0]), "+f"(d[1]), "+f"(d[2]), "+f"(d[3])
        : "r"(a[0]), "r"(a[1]), "r"(a[2]), "r"(a[3]), "r"(b[0]), "r"(b[1]));
}
// bf16 hi/lo split (attention path)
__device__ __forceinline__ void split1(float x, unsigned short& h, unsigned short& l) {
    __nv_bfloat16 hb = __float2bfloat16(x);
    float hf = __bfloat162float(hb);
    __nv_bfloat16 lb = __float2bfloat16(x - hf);
    h = __bfloat16_as_ushort(hb);
    l = __bfloat16_as_ushort(lb);
}
// fp16 hi/lo split (GEMM activation path)
__device__ __forceinline__ void split1h(float x, unsigned short& h, unsigned short& l) {
    __half hb = __float2half_rn(x);
    float hf = __half2float(hb);
    __half lb = __float2half_rn(x - hf);
    h = __half_as_ushort(hb);
    l = __half_as_ushort(lb);
}
// swizzled offset inside a 64B-wide tile: (row, 16B-chunk c in 0..3)
__device__ __forceinline__ uint32_t tile_off(int r, int c) {
    return (uint32_t)(((r >> 1) * 128) + (((((r & 1) << 2) | c) ^ ((r >> 1) & 7)) << 4));
}

// ---------------- LayerNorm with fp16 hi/lo split output ----------------
__global__ __launch_bounds__(256) void ln_split(const float* __restrict__ x,
                                                const float* __restrict__ gamma,
                                                const float* __restrict__ beta,
                                                __half* __restrict__ oh,
                                                __half* __restrict__ ol)
{
    int row = blockIdx.x;
    const float4* xr = reinterpret_cast<const float4*>(x + (size_t)row * DD);
    float4 v = xr[threadIdx.x];

    float s  = v.x + v.y + v.z + v.w;
    float sq = v.x*v.x + v.y*v.y + v.z*v.z + v.w*v.w;
    #pragma unroll
    for (int o = 16; o > 0; o >>= 1) {
        s  += __shfl_xor_sync(0xffffffffu, s,  o);
        sq += __shfl_xor_sync(0xffffffffu, sq, o);
    }
    __shared__ float ps[8], psq[8];
    int wid = threadIdx.x >> 5, lane = threadIdx.x & 31;
    if (lane == 0) { ps[wid] = s; psq[wid] = sq; }
    __syncthreads();
    float ts = 0.f, tsq = 0.f;
    #pragma unroll
    for (int i = 0; i < 8; i++) { ts += ps[i]; tsq += psq[i]; }

    float mu   = ts * (1.0f / DD);
    float var  = tsq * (1.0f / DD) - mu * mu;
    float rstd = rsqrtf(var + 1e-5f);

    float4 g = reinterpret_cast<const float4*>(gamma)[threadIdx.x];
    float4 b = reinterpret_cast<const float4*>(beta )[threadIdx.x];
    float o0 = (v.x - mu) * rstd * g.x + b.x;
    float o1 = (v.y - mu) * rstd * g.y + b.y;
    float o2 = (v.z - mu) * rstd * g.z + b.z;
    float o3 = (v.w - mu) * rstd * g.w + b.w;

    unsigned short h0,h1,h2,h3, l0,l1,l2,l3;
    split1h(o0,h0,l0); split1h(o1,h1,l1); split1h(o2,h2,l2); split1h(o3,h3,l3);
    uint2 hv = make_uint2((uint32_t)h0 | ((uint32_t)h1<<16), (uint32_t)h2 | ((uint32_t)h3<<16));
    uint2 lv = make_uint2((uint32_t)l0 | ((uint32_t)l1<<16), (uint32_t)l2 | ((uint32_t)l3<<16));
    reinterpret_cast<uint2*>(oh + (size_t)row*DD)[threadIdx.x] = hv;
    reinterpret_cast<uint2*>(ol + (size_t)row*DD)[threadIdx.x] = lv;
}

// ---------------- all-weights transpose + fp16 quantize (single launch) ----------------
__global__ __launch_bounds__(256) void wsplit_all(
    const float* __restrict__ Wq, const float* __restrict__ Wk,
    const float* __restrict__ Wv, const float* __restrict__ Wo,
    const float* __restrict__ W1, const float* __restrict__ W2,
    __half* __restrict__ qkvt, __half* __restrict__ wot,
    __half* __restrict__ w1t,  __half* __restrict__ w2t)
{
    int z = blockIdx.z;
    const float* W;
    __half* Bt;
    int K, N, n0, k0;
    if (z < 4) {
        W  = (z==0) ? Wq : (z==1) ? Wk : (z==2) ? Wv : Wo;
        Bt = (z<3) ? qkvt + (size_t)z*DD*DD : wot;
        K = DD; N = DD;
        n0 = blockIdx.x * 32; k0 = blockIdx.y * 32;
    } else if (z < 8) {
        W = W1; Bt = w1t; K = DD; N = FF;
        n0 = (z-4)*1024 + blockIdx.x * 32; k0 = blockIdx.y * 32;
    } else {
        W = W2; Bt = w2t; K = FF; N = DD;
        n0 = blockIdx.x * 32; k0 = (z-8)*1024 + blockIdx.y * 32;
    }

    __shared__ float t[32][33];
    int tx = threadIdx.x & 31, ty = threadIdx.x >> 5;
    #pragma unroll
    for (int r = 0; r < 4; r++)
        t[ty + 8*r][tx] = W[(size_t)(k0 + ty + 8*r) * N + n0 + tx];
    __syncthreads();
    #pragma unroll
    for (int r = 0; r < 4; r++) {
        int n = ty + 8*r, k = tx;
        Bt[(size_t)(n0 + n) * K + k0 + k] = __float2half_rn(t[k][n]);
    }
}

// ---------------- concat q/k/v biases ----------------
__global__ void bias3(const float* a, const float* b, const float* c, float* o) {
    int i = blockIdx.x * 256 + threadIdx.x;
    o[i] = (i < DD) ? a[i] : (i < 2*DD) ? b[i - DD] : c[i - 2*DD];
}

// ---------------- fp16 2-product warp-MMA GEMM: BK=32, 3-stage, 1 barrier/chunk ----------------
// C = (Ah + Al) @ B^T, A fp16 hi/lo, B single fp16, fp32 accum.
#define MBK 32
#define SOFF_AHI 0
#define SOFF_ALO 8192
#define SOFF_B   16384
#define MSTAGE 24576
#define MSMEM (3*MSTAGE)

#define MODE_QKV3       1
#define MODE_RESID      2
#define MODE_RELU_SPLIT 3

__global__ __launch_bounds__(256, 2) void gemm_mma(
    const __half* __restrict__ Ah, const __half* __restrict__ Al,
    const __half* __restrict__ Bv,
    const float* __restrict__ bias, const float* __restrict__ resid,
    float* __restrict__ Cf,
    unsigned short* __restrict__ Ch, unsigned short* __restrict__ Cl,
    int M, int K, int N, int mode)
{
    extern __shared__ char smraw[];
    const uint32_t smbase = smem_u32(smraw);

    const int tid  = threadIdx.x;
    const int warp = tid >> 5;
    const int lane = tid & 31;
    const int warpMoff = (warp & 1) * 64;
    const int warpNoff = (warp >> 1) * 32;
    const int mBase = blockIdx.y * 128;
    const int nBase = blockIdx.x * 128;
    const int nk = K / MBK;

    const int g = lane >> 3, l8 = lane & 7;
    uint32_t aoff[2][4], boff[2][2];
    #pragma unroll
    for (int ks = 0; ks < 2; ks++) {
        #pragma unroll
        for (int mt = 0; mt < 4; mt++)
            aoff[ks][mt] = tile_off(warpMoff + mt*16 + (g & 1)*8 + l8, 2*ks + (g >> 1));
        #pragma unroll
        for (int p = 0; p < 2; p++)
            boff[ks][p]  = tile_off(warpNoff + p*16 + (g >> 1)*8 + l8, 2*ks + (g & 1));
    }

    auto load_stage = [&](int chunk, int s) {
        const int k0 = chunk * MBK;
        uint32_t sb = smbase + (uint32_t)s * MSTAGE;
        #pragma unroll
        for (int h = 0; h < 2; h++) {
            int id = tid + h * 256;
            int r = id >> 2, c = id & 3;
            uint32_t so = tile_off(r, c);
            size_t ga = ((size_t)(mBase + r) * K + k0 + c*8) * 2;
            size_t gb = ((size_t)(nBase + r) * K + k0 + c*8) * 2;
            cp16(sb + SOFF_AHI + so, (const char*)Ah + ga);
            cp16(sb + SOFF_ALO + so, (const char*)Al + ga);
            cp16(sb + SOFF_B   + so, (const char*)Bv + gb);
        }
        cp_commit();
    };

    // 2-deep prefetch into a 3-stage ring
    load_stage(0, 0);
    load_stage(1, 1);

    float acc[4][4][4];
    #pragma unroll
    for (int mt = 0; mt < 4; mt++)
        #pragma unroll
        for (int nt = 0; nt < 4; nt++)
            #pragma unroll
            for (int e = 0; e < 4; e++) acc[mt][nt][e] = 0.f;

    for (int chunk = 0; chunk < nk; chunk++) {
        const int s = chunk % 3;
        if (chunk + 1 < nk) asm volatile("cp.async.wait_group 1;" ::: "memory");
        else                asm volatile("cp.async.wait_group 0;" ::: "memory");
        __syncthreads();
        if (chunk + 2 < nk) load_stage(chunk + 2, (chunk + 2) % 3);

        const uint32_t sb = smbase + (uint32_t)s * MSTAGE;
        #pragma unroll
        for (int ks = 0; ks < 2; ks++) {
            uint32_t bfr[4][2];
            #pragma unroll
            for (int p = 0; p < 2; p++)
                ldsm4(&bfr[2*p][0], sb + SOFF_B + boff[ks][p]);
            #pragma unroll
            for (int mt = 0; mt < 4; mt++) {
                uint32_t ahi[4], alo[4];
                ldsm4(ahi, sb + SOFF_AHI + aoff[ks][mt]);
                ldsm4(alo, sb + SOFF_ALO + aoff[ks][mt]);
                #pragma unroll
                for (int nt = 0; nt < 4; nt++) {
                    mma_f16(acc[mt][nt], ahi, bfr[nt]);
                    mma_f16(acc[mt][nt], alo, bfr[nt]);
                }
            }
        }
    }

    // ---------------- epilogue ----------------
    const int rl = lane >> 2;
    const int cl = (lane & 3) * 2;

    #pragma unroll
    for (int mt = 0; mt < 4; mt++) {
        #pragma unroll
        for (int nt = 0; nt < 4; nt++) {
            int gr0 = mBase + warpMoff + mt*16 + rl;
            int gc  = nBase + warpNoff + nt*8 + cl;
            float b0 = __ldg(&bias[gc]);
            float b1 = __ldg(&bias[gc + 1]);
            float v00 = acc[mt][nt][0] + b0, v01 = acc[mt][nt][1] + b1;
            float v10 = acc[mt][nt][2] + b0, v11 = acc[mt][nt][3] + b1;

            if (mode == MODE_QKV3) {
                int t = gc >> 10;
                int within = gc & 1023;
                int h = within >> 6, jj = within & 63;
                int p = jj >> 1;
                float inv = expf(-0.28782313663f * (float)p);   // 10000^(-p/32)
                #pragma unroll
                for (int rr = 0; rr < 2; rr++) {
                    int row = gr0 + rr*8;
                    int b = row >> 11, sI = row & 2047;
                    float w0 = rr ? v10 : v00;
                    float w1 = rr ? v11 : v01;
                    if (t < 2) {
                        float sn, cs;
                        sincosf((float)sI * inv, &sn, &cs);
                        float r0 = w0 * cs - w1 * sn;
                        float r1 = w0 * sn + w1 * cs;
                        if (t == 0) { r0 *= 0.125f; r1 *= 0.125f; }
                        w0 = r0; w1 = r1;
                    }
                    // attention consumes bf16 hi/lo
                    unsigned short h0,l0,h1,l1;
                    split1(w0, h0, l0);
                    split1(w1, h1, l1);
                    size_t ob = (size_t)t * NN * DD +
                                ((size_t)((b*HH + h)*SS + sI)) * HD + jj;
                    reinterpret_cast<uint32_t*>(Ch)[ob >> 1] = (uint32_t)h0 | ((uint32_t)h1 << 16);
                    reinterpret_cast<uint32_t*>(Cl)[ob >> 1] = (uint32_t)l0 | ((uint32_t)l1 << 16);
                }
            } else if (mode == MODE_RESID) {
                #pragma unroll
                for (int rr = 0; rr < 2; rr++) {
                    int row = gr0 + rr*8;
                    size_t ob = (size_t)row * N + gc;
                    float2 rv = *reinterpret_cast<const float2*>(resid + ob);
                    float2 o = rr ? make_float2(v10 + rv.x, v11 + rv.y)
                                  : make_float2(v00 + rv.x, v01 + rv.y);
                    *reinterpret_cast<float2*>(Cf + ob) = o;
                }
            } else { // MODE_RELU_SPLIT -> fp16 hi/lo
                #pragma unroll
                for (int rr = 0; rr < 2; rr++) {
                    int row = gr0 + rr*8;
                    size_t ob = (size_t)row * N + gc;
                    float w0 = fmaxf(rr ? v10 : v00, 0.f);
                    float w1 = fmaxf(rr ? v11 : v01, 0.f);
                    unsigned short h0,l0,h1,l1;
                    split1h(w0, h0, l0);
                    split1h(w1, h1, l1);
                    reinterpret_cast<uint32_t*>(Ch)[ob >> 1] = (uint32_t)h0 | ((uint32_t)h1 << 16);
                    reinterpret_cast<uint32_t*>(Cl)[ob >> 1] = (uint32_t)l0 | ((uint32_t)l1 << 16);
                }
            }
        }
    }
}

// ---------------- split-bf16 MMA flash attention (R9 structure; fp16 output split) ----------------
#define AT_SQH   0
#define AT_SQL   16384
#define AT_STAGE 32768
#define AT_SSZ   32768
#define AT_KH    0
#define AT_KL    8192
#define AT_VH    16384
#define AT_VL    24576
#define ATTN_SMEM (32768 + 2*32768)

__global__ __launch_bounds__(256, 2) void attn_mma(
    const __nv_bfloat16* __restrict__ Qh, const __nv_bfloat16* __restrict__ Ql,
    const __nv_bfloat16* __restrict__ Kh, const __nv_bfloat16* __restrict__ Kl,
    const __nv_bfloat16* __restrict__ Vh, const __nv_bfloat16* __restrict__ Vl,
    unsigned short* __restrict__ Oh, unsigned short* __restrict__ Ol)
{
    extern __shared__ char smraw[];
    const uint32_t sm = smem_u32(smraw);
    const int tid = threadIdx.x, warp = tid >> 5, lane = tid & 31;
    const int bh = blockIdx.y;
    const int q0 = blockIdx.x * 128;
    const int g = lane >> 3, l8 = lane & 7;
    const int rl = lane >> 2, cl = (lane & 3) * 2;

    // load Q tiles (hi/lo), part of first commit group
    #pragma unroll
    for (int t = 0; t < 8; t++) {
        int buf = t >> 2;                    // 0=hi,1=lo
        int w = (t & 3) * 256 + tid;         // 0..1023
        int r = w >> 3, c = w & 7;
        uint32_t off = (buf ? AT_SQL : AT_SQH) + (c >> 2) * 8192 + tile_off(r, c & 3);
        const char* gp = (const char*)(buf ? Ql : Qh) +
                         ((size_t)((size_t)bh * SS + q0 + r) * HD + c * 8) * 2;
        cp16(sm + off, gp);
    }

    auto load_kv = [&](int kb, int s) {
        uint32_t sb = sm + AT_STAGE + (uint32_t)s * AT_SSZ;
        #pragma unroll
        for (int t = 0; t < 8; t++) {
            int buf = t >> 1;                // 0=Kh 1=Kl 2=Vh 3=Vl
            int w = (t & 1) * 256 + tid;     // 0..511
            int r = w >> 3, c = w & 7;
            uint32_t off = (uint32_t)buf * 8192 + (c >> 2) * 4096 + tile_off(r, c & 3);
            const __nv_bfloat16* src = (buf == 0) ? Kh : (buf == 1) ? Kl : (buf == 2) ? Vh : Vl;
            const char* gp = (const char*)src + ((size_t)((size_t)bh * SS + kb + r) * HD + c * 8) * 2;
            cp16(sb + off, gp);
        }
        cp_commit();
    };

    load_kv(0, 0);
    load_kv(64, 1);

    float m0 = -1e30f, m1 = -1e30f, l0 = 0.f, l1 = 0.f;
    float acc[8][4];
    #pragma unroll
    for (int nt = 0; nt < 8; nt++)
        #pragma unroll
        for (int e = 0; e < 4; e++) acc[nt][e] = 0.f;

    const int NT = SS / 64;
    for (int it = 0; it < NT; it++) {
        if (it + 1 < NT) asm volatile("cp.async.wait_group 1;" ::: "memory");
        else             asm volatile("cp.async.wait_group 0;" ::: "memory");
        __syncthreads();
        const uint32_t sb = sm + AT_STAGE + (uint32_t)(it & 1) * AT_SSZ;

        // ---- S = Q K^T (split 3-product) ----
        float sacc[8][4];
        #pragma unroll
        for (int nt = 0; nt < 8; nt++)
            #pragma unroll
            for (int e = 0; e < 4; e++) sacc[nt][e] = 0.f;

        #pragma unroll
        for (int ks = 0; ks < 4; ks++) {
            uint32_t qoff = (uint32_t)((ks >> 1) * 8192) +
                            tile_off(warp*16 + (g & 1)*8 + l8, 2*(ks & 1) + (g >> 1));
            uint32_t qh4[4], ql4[4];
            ldsm4(qh4, sm + AT_SQH + qoff);
            ldsm4(ql4, sm + AT_SQL + qoff);
            uint32_t kh4[4][4], kl4[4][4];
            #pragma unroll
            for (int p = 0; p < 4; p++) {
                uint32_t ko = (uint32_t)((ks >> 1) * 4096) +
                              tile_off(p*16 + (g >> 1)*8 + l8, 2*(ks & 1) + (g & 1));
                ldsm4(kh4[p], sb + AT_KH + ko);
                ldsm4(kl4[p], sb + AT_KL + ko);
            }
            #pragma unroll
            for (int nt = 0; nt < 8; nt++) {
                const uint32_t* bhk = &kh4[nt >> 1][(nt & 1) * 2];
                const uint32_t* blk = &kl4[nt >> 1][(nt & 1) * 2];
                mma_bf16(sacc[nt], qh4, bhk);
                mma_bf16(sacc[nt], qh4, blk);
                mma_bf16(sacc[nt], ql4, bhk);
            }
        }

        // ---- online softmax ----
        float mx0 = -1e30f, mx1 = -1e30f;
        #pragma unroll
        for (int nt = 0; nt < 8; nt++) {
            mx0 = fmaxf(mx0, fmaxf(sacc[nt][0], sacc[nt][1]));
            mx1 = fmaxf(mx1, fmaxf(sacc[nt][2], sacc[nt][3]));
        }
        mx0 = fmaxf(mx0, __shfl_xor_sync(0xffffffffu, mx0, 1));
        mx0 = fmaxf(mx0, __shfl_xor_sync(0xffffffffu, mx0, 2));
        mx1 = fmaxf(mx1, __shfl_xor_sync(0xffffffffu, mx1, 1));
        mx1 = fmaxf(mx1, __shfl_xor_sync(0xffffffffu, mx1, 2));

        float mn0 = fmaxf(m0, mx0), mn1 = fmaxf(m1, mx1);
        float a0 = __expf(m0 - mn0), a1 = __expf(m1 - mn1);
        float rs0 = 0.f, rs1 = 0.f;
        #pragma unroll
        for (int nt = 0; nt < 8; nt++) {
            sacc[nt][0] = __expf(sacc[nt][0] - mn0);
            sacc[nt][1] = __expf(sacc[nt][1] - mn0);
            sacc[nt][2] = __expf(sacc[nt][2] - mn1);
            sacc[nt][3] = __expf(sacc[nt][3] - mn1);
            rs0 += sacc[nt][0] + sacc[nt][1];
            rs1 += sacc[nt][2] + sacc[nt][3];
        }
        rs0 += __shfl_xor_sync(0xffffffffu, rs0, 1);
        rs0 += __shfl_xor_sync(0xffffffffu, rs0, 2);
        rs1 += __shfl_xor_sync(0xffffffffu, rs1, 1);
        rs1 += __shfl_xor_sync(0xffffffffu, rs1, 2);
        l0 = l0 * a0 + rs0;  m0 = mn0;
        l1 = l1 * a1 + rs1;  m1 = mn1;
        #pragma unroll
        for (int nt = 0; nt < 8; nt++) {
            acc[nt][0] *= a0; acc[nt][1] *= a0;
            acc[nt][2] *= a1; acc[nt][3] *= a1;
        }

        // ---- O += P V (split 3-product); V row-major, trans ldmatrix ----
        #pragma unroll
        for (int ks = 0; ks < 4; ks++) {
            uint32_t aH[4], aL[4];
            #pragma unroll
            for (int half = 0; half < 2; half++) {
                int nt = 2*ks + half;
                unsigned short h0,l0s,h1,l1s,h2,l2s,h3,l3s;
                split1(sacc[nt][0], h0, l0s);
                split1(sacc[nt][1], h1, l1s);
                split1(sacc[nt][2], h2, l2s);
                split1(sacc[nt][3], h3, l3s);
                aH[half*2 + 0] = (uint32_t)h0  | ((uint32_t)h1  << 16);
                aH[half*2 + 1] = (uint32_t)h2  | ((uint32_t)h3  << 16);
                aL[half*2 + 0] = (uint32_t)l0s | ((uint32_t)l1s << 16);
                aL[half*2 + 1] = (uint32_t)l2s | ((uint32_t)l3s << 16);
            }
            uint32_t vh4[4][4], vl4[4][4];
            int vrow = 16*ks + (g & 1)*8 + l8;
            #pragma unroll
            for (int p = 0; p < 4; p++) {
                int c = p*2 + (g >> 1);            // 16B d-chunk 0..7
                uint32_t vo = (uint32_t)((c >> 2) * 4096) + tile_off(vrow, c & 3);
                ldsm4t(vh4[p], sb + AT_VH + vo);
                ldsm4t(vl4[p], sb + AT_VL + vo);
            }
            #pragma unroll
            for (int nt = 0; nt < 8; nt++) {
                const uint32_t* bhv = &vh4[nt >> 1][(nt & 1) * 2];
                const uint32_t* blv = &vl4[nt >> 1][(nt & 1) * 2];
                mma_bf16(acc[nt], aH, bhv);
                mma_bf16(acc[nt], aL, bhv);
                mma_bf16(acc[nt], aH, blv);
            }
        }

        __syncthreads();
        if (it + 2 < NT) load_kv((it + 2) * 64, it & 1);
    }

    // ---- epilogue: normalize, split to fp16 hi/lo (feeds Wo GEMM), write [B,S,D] ----
    float i0 = 1.f / l0, i1 = 1.f / l1;
    int b = bh >> 4, h = bh & 15;
    int s0r = q0 + warp * 16 + rl;
    #pragma unroll
    for (int nt = 0; nt < 8; nt++) {
        int col = h * 64 + nt * 8 + cl;
        {
            float w0 = acc[nt][0] * i0, w1 = acc[nt][1] * i0;
            unsigned short h0,lo0,h1,lo1;
            split1h(w0, h0, lo0); split1h(w1, h1, lo1);
            size_t ob = (size_t)(b * SS + s0r) * DD + col;
            reinterpret_cast<uint32_t*>(Oh)[ob >> 1] = (uint32_t)h0  | ((uint32_t)h1  << 16);
            reinterpret_cast<uint32_t*>(Ol)[ob >> 1] = (uint32_t)lo0 | ((uint32_t)lo1 << 16);
        }
        {
            float w0 = acc[nt][2] * i1, w1 = acc[nt][3] * i1;
            unsigned short h0,lo0,h1,lo1;
            split1h(w0, h0, lo0); split1h(w1, h1, lo1);
            size_t ob = (size_t)(b * SS + s0r + 8) * DD + col;
            reinterpret_cast<uint32_t*>(Oh)[ob >> 1] = (uint32_t)h0  | ((uint32_t)h1  << 16);
            reinterpret_cast<uint32_t*>(Ol)[ob >> 1] = (uint32_t)lo0 | ((uint32_t)lo1 << 16);
        }
    }
}

// ---------------- host launch ----------------
extern "C" void kernel_launch(void* const* d_in, const int* in_sizes, int n_in,
                              void* d_out, int out_size)
{
    const float* x     = (const float*)d_in[0];
    const float* Wq    = (const float*)d_in[1];
    const float* bq    = (const float*)d_in[2];
    const float* Wk    = (const float*)d_in[3];
    const float* bk    = (const float*)d_in[4];
    const float* Wv    = (const float*)d_in[5];
    const float* bv    = (const float*)d_in[6];
    const float* Wo    = (const float*)d_in[7];
    const float* bo    = (const float*)d_in[8];
    const float* W1    = (const float*)d_in[9];
    const float* b1    = (const float*)d_in[10];
    const float* W2    = (const float*)d_in[11];
    const float* b2    = (const float*)d_in[12];
    const float* g1    = (const float*)d_in[13];
    const float* beta1 = (const float*)d_in[14];
    const float* g2    = (const float*)d_in[15];
    const float* beta2 = (const float*)d_in[16];
    float* out = (float*)d_out;

    float *x1, *bqkv;
    __half *xnh, *xnl, *xn2h, *xn2l, *ath, *atl, *hh, *hl;
    __nv_bfloat16 *qkvbh, *qkvbl;
    __half *qkvt, *wot, *w1t, *w2t;
    cudaGetSymbolAddress((void**)&x1,    g_x1);
    cudaGetSymbolAddress((void**)&bqkv,  g_bqkv);
    cudaGetSymbolAddress((void**)&xnh,   g_xn_h);
    cudaGetSymbolAddress((void**)&xnl,   g_xn_l);
    cudaGetSymbolAddress((void**)&xn2h,  g_xn2_h);
    cudaGetSymbolAddress((void**)&xn2l,  g_xn2_l);
    cudaGetSymbolAddress((void**)&ath,   g_at_h);
    cudaGetSymbolAddress((void**)&atl,   g_at_l);
    cudaGetSymbolAddress((void**)&hh,    g_h_h);
    cudaGetSymbolAddress((void**)&hl,    g_h_l);
    cudaGetSymbolAddress((void**)&qkvbh, g_qkvb_h);
    cudaGetSymbolAddress((void**)&qkvbl, g_qkvb_l);
    cudaGetSymbolAddress((void**)&qkvt,  g_qkvt);
    cudaGetSymbolAddress((void**)&wot,   g_wot);
    cudaGetSymbolAddress((void**)&w1t,   g_w1t);
    cudaGetSymbolAddress((void**)&w2t,   g_w2t);

    cudaFuncSetAttribute(gemm_mma, cudaFuncAttributeMaxDynamicSharedMemorySize, MSMEM);
    cudaFuncSetAttribute(attn_mma, cudaFuncAttributeMaxDynamicSharedMemorySize, ATTN_SMEM);

    // 1: all weight transposes + fp16 quantize in one launch
    wsplit_all<<<dim3(32, 32, 12), 256>>>(Wq, Wk, Wv, Wo, W1, W2,
                                          qkvt, wot, w1t, w2t);
    // 2
    bias3<<<3*DD/256, 256>>>(bq, bk, bv, bqkv);
    // 3: LN1 -> fp16 split
    ln_split<<<NN, 256>>>(x, g1, beta1, xnh, xnl);

    // 4: fused QKV projection + bias + RoPE; emits bf16 hi/lo q,k,v for attention
    gemm_mma<<<dim3(3*DD/128, NN/128), 256, MSMEM>>>(
        xnh, xnl, qkvt, bqkv, nullptr, nullptr,
        (unsigned short*)qkvbh, (unsigned short*)qkvbl,
        NN, DD, 3*DD, MODE_QKV3);

    __nv_bfloat16* qh = qkvbh;
    __nv_bfloat16* ql = qkvbl;
    __nv_bfloat16* kh = qkvbh + (size_t)NN*DD;
    __nv_bfloat16* kl = qkvbl + (size_t)NN*DD;
    __nv_bfloat16* vh = qkvbh + 2*(size_t)NN*DD;
    __nv_bfloat16* vl = qkvbl + 2*(size_t)NN*DD;

    // 5: MMA flash attention -> fp16 hi/lo attn output [B,S,D]
    attn_mma<<<dim3(SS/128, BB*HH), 256, ATTN_SMEM>>>(
        qh, ql, kh, kl, vh, vl,
        (unsigned short*)ath, (unsigned short*)atl);

    // 6: x1 = x + attn @ Wo + bo
    gemm_mma<<<dim3(DD/128, NN/128), 256, MSMEM>>>(
        ath, atl, wot, bo, x, x1, nullptr, nullptr,
        NN, DD, DD, MODE_RESID);

    // 7: LN2 -> fp16 split
    ln_split<<<NN, 256>>>(x1, g2, beta2, xn2h, xn2l);

    // 8: FFN up: relu + fp16 split epilogue
    gemm_mma<<<dim3(FF/128, NN/128), 256, MSMEM>>>(
        xn2h, xn2l, w1t, b1, nullptr, nullptr,
        (unsigned short*)hh, (unsigned short*)hl,
        NN, DD, FF, MODE_RELU_SPLIT);

    // 9: FFN down + residual -> out
    gemm_mma<<<dim3(DD/128, NN/128), 256, MSMEM>>>(
        hh, hl, w2t, b2, x1, out, nullptr, nullptr,
        NN, FF, DD, MODE_RESID);
}

// round 14
// speedup vs baseline: 1.4051x; 1.1060x over previous
#include <cuda_runtime.h>
#include <cuda_fp16.h>
#include <math.h>
#include <stdint.h>

#define BB 2
#define SS 2048
#define DD 1024
#define HH 16
#define HD 64
#define FF 4096
#define NN (BB*SS)   // 4096 tokens

// ---------------- scratch (static device globals; no allocs) ----------------
__device__ float g_x1  [NN*DD];      // x + attn_out
__device__ __half g_xn_h [NN*DD], g_xn_l [NN*DD];        // LN1 out, fp16 hi/lo
__device__ __half g_xn2_h[NN*DD], g_xn2_l[NN*DD];        // LN2 out
__device__ __half g_at_h [NN*DD], g_at_l [NN*DD];        // attn out [B,S,D] fp16 hi/lo
__device__ __half g_qkvb_h[3u*NN*DD], g_qkvb_l[3u*NN*DD]; // q,k,v fp16 hi/lo [t][B,H,S,hd]
__device__ __half g_h_h  [(size_t)NN*FF], g_h_l[(size_t)NN*FF];  // FFN hidden fp16 hi/lo
__device__ __half g_qkvt [3*DD*DD];  // weights fp16 single [3072,1024]
__device__ __half g_wot  [DD*DD];
__device__ __half g_w1t  [FF*DD];
__device__ __half g_w2t  [DD*FF];
__device__ float g_bqkv[3*DD];

// ---------------- helpers ----------------
__device__ __forceinline__ uint32_t smem_u32(const void* p) {
    return (uint32_t)__cvta_generic_to_shared(p);
}
__device__ __forceinline__ void cp16(uint32_t s, const void* g) {
    asm volatile("cp.async.cg.shared.global [%0], [%1], 16;" :: "r"(s), "l"(g));
}
__device__ __forceinline__ void cp_commit() {
    asm volatile("cp.async.commit_group;" ::: "memory");
}
__device__ __forceinline__ void ldsm4(uint32_t* r, uint32_t addr) {
    asm volatile("ldmatrix.sync.aligned.m8n8.x4.shared.b16 {%0,%1,%2,%3}, [%4];"
        : "=r"(r[0]), "=r"(r[1]), "=r"(r[2]), "=r"(r[3]) : "r"(addr));
}
__device__ __forceinline__ void ldsm4t(uint32_t* r, uint32_t addr) {
    asm volatile("ldmatrix.sync.aligned.m8n8.x4.trans.shared.b16 {%0,%1,%2,%3}, [%4];"
        : "=r"(r[0]), "=r"(r[1]), "=r"(r[2]), "=r"(r[3]) : "r"(addr));
}
__device__ __forceinline__ void mma_f16(float* d, const uint32_t* a, const uint32_t* b) {
    asm volatile("mma.sync.aligned.m16n8k16.row.col.f32.f16.f16.f32 "
        "{%0,%1,%2,%3}, {%4,%5,%6,%7}, {%8,%9}, {%0,%1,%2,%3};"
        : "+f"(d[0]), "+f"(d[1]), "+f"(d[2]), "+f"(d[3])
        : "r"(a[0]), "r"(a[1]), "r"(a[2]), "r"(a[3]), "r"(b[0]), "r"(b[1]));
}
// fp16 hi/lo split
__device__ __forceinline__ void split1h(float x, unsigned short& h, unsigned short& l) {
    __half hb = __float2half_rn(x);
    float hf = __half2float(hb);
    __half lb = __float2half_rn(x - hf);
    h = __half_as_ushort(hb);
    l = __half_as_ushort(lb);
}
// swizzled offset inside a 64B-wide tile: (row, 16B-chunk c in 0..3)
__device__ __forceinline__ uint32_t tile_off(int r, int c) {
    return (uint32_t)(((r >> 1) * 128) + (((((r & 1) << 2) | c) ^ ((r >> 1) & 7)) << 4));
}

// ---------------- LayerNorm with fp16 hi/lo split output ----------------
__global__ __launch_bounds__(256) void ln_split(const float* __restrict__ x,
                                                const float* __restrict__ gamma,
                                                const float* __restrict__ beta,
                                                __half* __restrict__ oh,
                                                __half* __restrict__ ol)
{
    int row = blockIdx.x;
    const float4* xr = reinterpret_cast<const float4*>(x + (size_t)row * DD);
    float4 v = xr[threadIdx.x];

    float s  = v.x + v.y + v.z + v.w;
    float sq = v.x*v.x + v.y*v.y + v.z*v.z + v.w*v.w;
    #pragma unroll
    for (int o = 16; o > 0; o >>= 1) {
        s  += __shfl_xor_sync(0xffffffffu, s,  o);
        sq += __shfl_xor_sync(0xffffffffu, sq, o);
    }
    __shared__ float ps[8], psq[8];
    int wid = threadIdx.x >> 5, lane = threadIdx.x & 31;
    if (lane == 0) { ps[wid] = s; psq[wid] = sq; }
    __syncthreads();
    float ts = 0.f, tsq = 0.f;
    #pragma unroll
    for (int i = 0; i < 8; i++) { ts += ps[i]; tsq += psq[i]; }

    float mu   = ts * (1.0f / DD);
    float var  = tsq * (1.0f / DD) - mu * mu;
    float rstd = rsqrtf(var + 1e-5f);

    float4 g = reinterpret_cast<const float4*>(gamma)[threadIdx.x];
    float4 b = reinterpret_cast<const float4*>(beta )[threadIdx.x];
    float o0 = (v.x - mu) * rstd * g.x + b.x;
    float o1 = (v.y - mu) * rstd * g.y + b.y;
    float o2 = (v.z - mu) * rstd * g.z + b.z;
    float o3 = (v.w - mu) * rstd * g.w + b.w;

    unsigned short h0,h1,h2,h3, l0,l1,l2,l3;
    split1h(o0,h0,l0); split1h(o1,h1,l1); split1h(o2,h2,l2); split1h(o3,h3,l3);
    uint2 hv = make_uint2((uint32_t)h0 | ((uint32_t)h1<<16), (uint32_t)h2 | ((uint32_t)h3<<16));
    uint2 lv = make_uint2((uint32_t)l0 | ((uint32_t)l1<<16), (uint32_t)l2 | ((uint32_t)l3<<16));
    reinterpret_cast<uint2*>(oh + (size_t)row*DD)[threadIdx.x] = hv;
    reinterpret_cast<uint2*>(ol + (size_t)row*DD)[threadIdx.x] = lv;
}

// ---------------- all-weights transpose + fp16 quantize (single launch) ----------------
__global__ __launch_bounds__(256) void wsplit_all(
    const float* __restrict__ Wq, const float* __restrict__ Wk,
    const float* __restrict__ Wv, const float* __restrict__ Wo,
    const float* __restrict__ W1, const float* __restrict__ W2,
    __half* __restrict__ qkvt, __half* __restrict__ wot,
    __half* __restrict__ w1t,  __half* __restrict__ w2t)
{
    int z = blockIdx.z;
    const float* W;
    __half* Bt;
    int K, N, n0, k0;
    if (z < 4) {
        W  = (z==0) ? Wq : (z==1) ? Wk : (z==2) ? Wv : Wo;
        Bt = (z<3) ? qkvt + (size_t)z*DD*DD : wot;
        K = DD; N = DD;
        n0 = blockIdx.x * 32; k0 = blockIdx.y * 32;
    } else if (z < 8) {
        W = W1; Bt = w1t; K = DD; N = FF;
        n0 = (z-4)*1024 + blockIdx.x * 32; k0 = blockIdx.y * 32;
    } else {
        W = W2; Bt = w2t; K = FF; N = DD;
        n0 = blockIdx.x * 32; k0 = (z-8)*1024 + blockIdx.y * 32;
    }

    __shared__ float t[32][33];
    int tx = threadIdx.x & 31, ty = threadIdx.x >> 5;
    #pragma unroll
    for (int r = 0; r < 4; r++)
        t[ty + 8*r][tx] = W[(size_t)(k0 + ty + 8*r) * N + n0 + tx];
    __syncthreads();
    #pragma unroll
    for (int r = 0; r < 4; r++) {
        int n = ty + 8*r, k = tx;
        Bt[(size_t)(n0 + n) * K + k0 + k] = __float2half_rn(t[k][n]);
    }
}

// ---------------- concat q/k/v biases ----------------
__global__ void bias3(const float* a, const float* b, const float* c, float* o) {
    int i = blockIdx.x * 256 + threadIdx.x;
    o[i] = (i < DD) ? a[i] : (i < 2*DD) ? b[i - DD] : c[i - 2*DD];
}

// ---------------- fp16 2-product warp-MMA GEMM: BK=32, 3-stage, 1 barrier/chunk ----------------
#define MBK 32
#define SOFF_AHI 0
#define SOFF_ALO 8192
#define SOFF_B   16384
#define MSTAGE 24576
#define MSMEM (3*MSTAGE)

#define MODE_QKV3       1
#define MODE_RESID      2
#define MODE_RELU_SPLIT 3

__global__ __launch_bounds__(256, 2) void gemm_mma(
    const __half* __restrict__ Ah, const __half* __restrict__ Al,
    const __half* __restrict__ Bv,
    const float* __restrict__ bias, const float* __restrict__ resid,
    float* __restrict__ Cf,
    unsigned short* __restrict__ Ch, unsigned short* __restrict__ Cl,
    int M, int K, int N, int mode)
{
    extern __shared__ char smraw[];
    const uint32_t smbase = smem_u32(smraw);

    const int tid  = threadIdx.x;
    const int warp = tid >> 5;
    const int lane = tid & 31;
    const int warpMoff = (warp & 1) * 64;
    const int warpNoff = (warp >> 1) * 32;
    const int mBase = blockIdx.y * 128;
    const int nBase = blockIdx.x * 128;
    const int nk = K / MBK;

    const int g = lane >> 3, l8 = lane & 7;
    uint32_t aoff[2][4], boff[2][2];
    #pragma unroll
    for (int ks = 0; ks < 2; ks++) {
        #pragma unroll
        for (int mt = 0; mt < 4; mt++)
            aoff[ks][mt] = tile_off(warpMoff + mt*16 + (g & 1)*8 + l8, 2*ks + (g >> 1));
        #pragma unroll
        for (int p = 0; p < 2; p++)
            boff[ks][p]  = tile_off(warpNoff + p*16 + (g >> 1)*8 + l8, 2*ks + (g & 1));
    }

    auto load_stage = [&](int chunk, int s) {
        const int k0 = chunk * MBK;
        uint32_t sb = smbase + (uint32_t)s * MSTAGE;
        #pragma unroll
        for (int h = 0; h < 2; h++) {
            int id = tid + h * 256;
            int r = id >> 2, c = id & 3;
            uint32_t so = tile_off(r, c);
            size_t ga = ((size_t)(mBase + r) * K + k0 + c*8) * 2;
            size_t gb = ((size_t)(nBase + r) * K + k0 + c*8) * 2;
            cp16(sb + SOFF_AHI + so, (const char*)Ah + ga);
            cp16(sb + SOFF_ALO + so, (const char*)Al + ga);
            cp16(sb + SOFF_B   + so, (const char*)Bv + gb);
        }
        cp_commit();
    };

    load_stage(0, 0);
    load_stage(1, 1);

    float acc[4][4][4];
    #pragma unroll
    for (int mt = 0; mt < 4; mt++)
        #pragma unroll
        for (int nt = 0; nt < 4; nt++)
            #pragma unroll
            for (int e = 0; e < 4; e++) acc[mt][nt][e] = 0.f;

    for (int chunk = 0; chunk < nk; chunk++) {
        const int s = chunk % 3;
        if (chunk + 1 < nk) asm volatile("cp.async.wait_group 1;" ::: "memory");
        else                asm volatile("cp.async.wait_group 0;" ::: "memory");
        __syncthreads();
        if (chunk + 2 < nk) load_stage(chunk + 2, (chunk + 2) % 3);

        const uint32_t sb = smbase + (uint32_t)s * MSTAGE;
        #pragma unroll
        for (int ks = 0; ks < 2; ks++) {
            uint32_t bfr[4][2];
            #pragma unroll
            for (int p = 0; p < 2; p++)
                ldsm4(&bfr[2*p][0], sb + SOFF_B + boff[ks][p]);
            #pragma unroll
            for (int mt = 0; mt < 4; mt++) {
                uint32_t ahi[4], alo[4];
                ldsm4(ahi, sb + SOFF_AHI + aoff[ks][mt]);
                ldsm4(alo, sb + SOFF_ALO + aoff[ks][mt]);
                #pragma unroll
                for (int nt = 0; nt < 4; nt++) {
                    mma_f16(acc[mt][nt], ahi, bfr[nt]);
                    mma_f16(acc[mt][nt], alo, bfr[nt]);
                }
            }
        }
    }

    // ---------------- epilogue ----------------
    const int rl = lane >> 2;
    const int cl = (lane & 3) * 2;

    #pragma unroll
    for (int mt = 0; mt < 4; mt++) {
        #pragma unroll
        for (int nt = 0; nt < 4; nt++) {
            int gr0 = mBase + warpMoff + mt*16 + rl;
            int gc  = nBase + warpNoff + nt*8 + cl;
            float b0 = __ldg(&bias[gc]);
            float b1 = __ldg(&bias[gc + 1]);
            float v00 = acc[mt][nt][0] + b0, v01 = acc[mt][nt][1] + b1;
            float v10 = acc[mt][nt][2] + b0, v11 = acc[mt][nt][3] + b1;

            if (mode == MODE_QKV3) {
                int t = gc >> 10;
                int within = gc & 1023;
                int h = within >> 6, jj = within & 63;
                int p = jj >> 1;
                float inv = expf(-0.28782313663f * (float)p);   // 10000^(-p/32)
                #pragma unroll
                for (int rr = 0; rr < 2; rr++) {
                    int row = gr0 + rr*8;
                    int b = row >> 11, sI = row & 2047;
                    float w0 = rr ? v10 : v00;
                    float w1 = rr ? v11 : v01;
                    if (t < 2) {
                        float sn, cs;
                        sincosf((float)sI * inv, &sn, &cs);
                        float r0 = w0 * cs - w1 * sn;
                        float r1 = w0 * sn + w1 * cs;
                        if (t == 0) { r0 *= 0.125f; r1 *= 0.125f; }
                        w0 = r0; w1 = r1;
                    }
                    // attention consumes fp16 hi/lo
                    unsigned short h0,l0,h1,l1;
                    split1h(w0, h0, l0);
                    split1h(w1, h1, l1);
                    size_t ob = (size_t)t * NN * DD +
                                ((size_t)((b*HH + h)*SS + sI)) * HD + jj;
                    reinterpret_cast<uint32_t*>(Ch)[ob >> 1] = (uint32_t)h0 | ((uint32_t)h1 << 16);
                    reinterpret_cast<uint32_t*>(Cl)[ob >> 1] = (uint32_t)l0 | ((uint32_t)l1 << 16);
                }
            } else if (mode == MODE_RESID) {
                #pragma unroll
                for (int rr = 0; rr < 2; rr++) {
                    int row = gr0 + rr*8;
                    size_t ob = (size_t)row * N + gc;
                    float2 rv = *reinterpret_cast<const float2*>(resid + ob);
                    float2 o = rr ? make_float2(v10 + rv.x, v11 + rv.y)
                                  : make_float2(v00 + rv.x, v01 + rv.y);
                    *reinterpret_cast<float2*>(Cf + ob) = o;
                }
            } else { // MODE_RELU_SPLIT -> fp16 hi/lo
                #pragma unroll
                for (int rr = 0; rr < 2; rr++) {
                    int row = gr0 + rr*8;
                    size_t ob = (size_t)row * N + gc;
                    float w0 = fmaxf(rr ? v10 : v00, 0.f);
                    float w1 = fmaxf(rr ? v11 : v01, 0.f);
                    unsigned short h0,l0,h1,l1;
                    split1h(w0, h0, l0);
                    split1h(w1, h1, l1);
                    reinterpret_cast<uint32_t*>(Ch)[ob >> 1] = (uint32_t)h0 | ((uint32_t)h1 << 16);
                    reinterpret_cast<uint32_t*>(Cl)[ob >> 1] = (uint32_t)l0 | ((uint32_t)l1 << 16);
                }
            }
        }
    }
}

// ---------------- fp16 2-product MMA flash attention ----------------
// S = (Qh+Ql)·Kh ; O += P_fp16·(Vh+Vl).  Stage: Kh | Vh | Vl (24 KB).
#define AT_SQH   0
#define AT_SQL   16384
#define AT_STAGE 32768
#define AT_SSZ   24576
#define AT_KH    0
#define AT_VH    8192
#define AT_VL    16384
#define ATTN_SMEM (32768 + 2*24576)

__global__ __launch_bounds__(256, 2) void attn_mma(
    const __half* __restrict__ Qh, const __half* __restrict__ Ql,
    const __half* __restrict__ Kh,
    const __half* __restrict__ Vh, const __half* __restrict__ Vl,
    unsigned short* __restrict__ Oh, unsigned short* __restrict__ Ol)
{
    extern __shared__ char smraw[];
    const uint32_t sm = smem_u32(smraw);
    const int tid = threadIdx.x, warp = tid >> 5, lane = tid & 31;
    const int bh = blockIdx.y;
    const int q0 = blockIdx.x * 128;
    const int g = lane >> 3, l8 = lane & 7;
    const int rl = lane >> 2, cl = (lane & 3) * 2;

    // load Q tiles (hi/lo), part of first commit group
    #pragma unroll
    for (int t = 0; t < 8; t++) {
        int buf = t >> 2;                    // 0=hi,1=lo
        int w = (t & 3) * 256 + tid;         // 0..1023
        int r = w >> 3, c = w & 7;
        uint32_t off = (buf ? AT_SQL : AT_SQH) + (c >> 2) * 8192 + tile_off(r, c & 3);
        const char* gp = (const char*)(buf ? Ql : Qh) +
                         ((size_t)((size_t)bh * SS + q0 + r) * HD + c * 8) * 2;
        cp16(sm + off, gp);
    }

    auto load_kv = [&](int kb, int s) {
        uint32_t sb = sm + AT_STAGE + (uint32_t)s * AT_SSZ;
        #pragma unroll
        for (int t = 0; t < 6; t++) {
            int buf = t >> 1;                // 0=Kh 1=Vh 2=Vl
            int w = (t & 1) * 256 + tid;     // 0..511
            int r = w >> 3, c = w & 7;
            uint32_t off = (uint32_t)buf * 8192 + (c >> 2) * 4096 + tile_off(r, c & 3);
            const __half* src = (buf == 0) ? Kh : (buf == 1) ? Vh : Vl;
            const char* gp = (const char*)src + ((size_t)((size_t)bh * SS + kb + r) * HD + c * 8) * 2;
            cp16(sb + off, gp);
        }
        cp_commit();
    };

    load_kv(0, 0);
    load_kv(64, 1);

    float m0 = -1e30f, m1 = -1e30f, l0 = 0.f, l1 = 0.f;
    float acc[8][4];
    #pragma unroll
    for (int nt = 0; nt < 8; nt++)
        #pragma unroll
        for (int e = 0; e < 4; e++) acc[nt][e] = 0.f;

    const int NT = SS / 64;
    for (int it = 0; it < NT; it++) {
        if (it + 1 < NT) asm volatile("cp.async.wait_group 1;" ::: "memory");
        else             asm volatile("cp.async.wait_group 0;" ::: "memory");
        __syncthreads();
        const uint32_t sb = sm + AT_STAGE + (uint32_t)(it & 1) * AT_SSZ;

        // ---- S = (Qh+Ql) K^T (2 products) ----
        float sacc[8][4];
        #pragma unroll
        for (int nt = 0; nt < 8; nt++)
            #pragma unroll
            for (int e = 0; e < 4; e++) sacc[nt][e] = 0.f;

        #pragma unroll
        for (int ks = 0; ks < 4; ks++) {
            uint32_t qoff = (uint32_t)((ks >> 1) * 8192) +
                            tile_off(warp*16 + (g & 1)*8 + l8, 2*(ks & 1) + (g >> 1));
            uint32_t qh4[4], ql4[4];
            ldsm4(qh4, sm + AT_SQH + qoff);
            ldsm4(ql4, sm + AT_SQL + qoff);
            #pragma unroll
            for (int p = 0; p < 4; p++) {
                uint32_t kh4[4];
                uint32_t ko = (uint32_t)((ks >> 1) * 4096) +
                              tile_off(p*16 + (g >> 1)*8 + l8, 2*(ks & 1) + (g & 1));
                ldsm4(kh4, sb + AT_KH + ko);
                #pragma unroll
                for (int half = 0; half < 2; half++) {
                    int nt = 2*p + half;
                    const uint32_t* bk = &kh4[half * 2];
                    mma_f16(sacc[nt], qh4, bk);
                    mma_f16(sacc[nt], ql4, bk);
                }
            }
        }

        // ---- online softmax ----
        float mx0 = -1e30f, mx1 = -1e30f;
        #pragma unroll
        for (int nt = 0; nt < 8; nt++) {
            mx0 = fmaxf(mx0, fmaxf(sacc[nt][0], sacc[nt][1]));
            mx1 = fmaxf(mx1, fmaxf(sacc[nt][2], sacc[nt][3]));
        }
        mx0 = fmaxf(mx0, __shfl_xor_sync(0xffffffffu, mx0, 1));
        mx0 = fmaxf(mx0, __shfl_xor_sync(0xffffffffu, mx0, 2));
        mx1 = fmaxf(mx1, __shfl_xor_sync(0xffffffffu, mx1, 1));
        mx1 = fmaxf(mx1, __shfl_xor_sync(0xffffffffu, mx1, 2));

        float mn0 = fmaxf(m0, mx0), mn1 = fmaxf(m1, mx1);
        float a0 = __expf(m0 - mn0), a1 = __expf(m1 - mn1);
        float rs0 = 0.f, rs1 = 0.f;
        #pragma unroll
        for (int nt = 0; nt < 8; nt++) {
            sacc[nt][0] = __expf(sacc[nt][0] - mn0);
            sacc[nt][1] = __expf(sacc[nt][1] - mn0);
            sacc[nt][2] = __expf(sacc[nt][2] - mn1);
            sacc[nt][3] = __expf(sacc[nt][3] - mn1);
            rs0 += sacc[nt][0] + sacc[nt][1];
            rs1 += sacc[nt][2] + sacc[nt][3];
        }
        rs0 += __shfl_xor_sync(0xffffffffu, rs0, 1);
        rs0 += __shfl_xor_sync(0xffffffffu, rs0, 2);
        rs1 += __shfl_xor_sync(0xffffffffu, rs1, 1);
        rs1 += __shfl_xor_sync(0xffffffffu, rs1, 2);
        l0 = l0 * a0 + rs0;  m0 = mn0;
        l1 = l1 * a1 + rs1;  m1 = mn1;
        #pragma unroll
        for (int nt = 0; nt < 8; nt++) {
            acc[nt][0] *= a0; acc[nt][1] *= a0;
            acc[nt][2] *= a1; acc[nt][3] *= a1;
        }

        // ---- O += P_fp16 (Vh+Vl) (2 products); V row-major, trans ldmatrix ----
        #pragma unroll
        for (int ks = 0; ks < 4; ks++) {
            uint32_t aP[4];
            #pragma unroll
            for (int half = 0; half < 2; half++) {
                int nt = 2*ks + half;
                __half p0 = __float2half_rn(sacc[nt][0]);
                __half p1 = __float2half_rn(sacc[nt][1]);
                __half p2 = __float2half_rn(sacc[nt][2]);
                __half p3 = __float2half_rn(sacc[nt][3]);
                aP[half*2 + 0] = (uint32_t)__half_as_ushort(p0) | ((uint32_t)__half_as_ushort(p1) << 16);
                aP[half*2 + 1] = (uint32_t)__half_as_ushort(p2) | ((uint32_t)__half_as_ushort(p3) << 16);
            }
            int vrow = 16*ks + (g & 1)*8 + l8;
            #pragma unroll
            for (int p = 0; p < 4; p++) {
                uint32_t vh4[4], vl4[4];
                int c = p*2 + (g >> 1);            // 16B d-chunk 0..7
                uint32_t vo = (uint32_t)((c >> 2) * 4096) + tile_off(vrow, c & 3);
                ldsm4t(vh4, sb + AT_VH + vo);
                ldsm4t(vl4, sb + AT_VL + vo);
                #pragma unroll
                for (int half = 0; half < 2; half++) {
                    int nt = 2*p + half;
                    mma_f16(acc[nt], aP, &vh4[half * 2]);
                    mma_f16(acc[nt], aP, &vl4[half * 2]);
                }
            }
        }

        __syncthreads();
        if (it + 2 < NT) load_kv((it + 2) * 64, it & 1);
    }

    // ---- epilogue: normalize, split to fp16 hi/lo (feeds Wo GEMM), write [B,S,D] ----
    float i0 = 1.f / l0, i1 = 1.f / l1;
    int b = bh >> 4, h = bh & 15;
    int s0r = q0 + warp * 16 + rl;
    #pragma unroll
    for (int nt = 0; nt < 8; nt++) {
        int col = h * 64 + nt * 8 + cl;
        {
            float w0 = acc[nt][0] * i0, w1 = acc[nt][1] * i0;
            unsigned short h0,lo0,h1,lo1;
            split1h(w0, h0, lo0); split1h(w1, h1, lo1);
            size_t ob = (size_t)(b * SS + s0r) * DD + col;
            reinterpret_cast<uint32_t*>(Oh)[ob >> 1] = (uint32_t)h0  | ((uint32_t)h1  << 16);
            reinterpret_cast<uint32_t*>(Ol)[ob >> 1] = (uint32_t)lo0 | ((uint32_t)lo1 << 16);
        }
        {
            float w0 = acc[nt][2] * i1, w1 = acc[nt][3] * i1;
            unsigned short h0,lo0,h1,lo1;
            split1h(w0, h0, lo0); split1h(w1, h1, lo1);
            size_t ob = (size_t)(b * SS + s0r + 8) * DD + col;
            reinterpret_cast<uint32_t*>(Oh)[ob >> 1] = (uint32_t)h0  | ((uint32_t)h1  << 16);
            reinterpret_cast<uint32_t*>(Ol)[ob >> 1] = (uint32_t)lo0 | ((uint32_t)lo1 << 16);
        }
    }
}

// ---------------- host launch ----------------
extern "C" void kernel_launch(void* const* d_in, const int* in_sizes, int n_in,
                              void* d_out, int out_size)
{
    const float* x     = (const float*)d_in[0];
    const float* Wq    = (const float*)d_in[1];
    const float* bq    = (const float*)d_in[2];
    const float* Wk    = (const float*)d_in[3];
    const float* bk    = (const float*)d_in[4];
    const float* Wv    = (const float*)d_in[5];
    const float* bv    = (const float*)d_in[6];
    const float* Wo    = (const float*)d_in[7];
    const float* bo    = (const float*)d_in[8];
    const float* W1    = (const float*)d_in[9];
    const float* b1    = (const float*)d_in[10];
    const float* W2    = (const float*)d_in[11];
    const float* b2    = (const float*)d_in[12];
    const float* g1    = (const float*)d_in[13];
    const float* beta1 = (const float*)d_in[14];
    const float* g2    = (const float*)d_in[15];
    const float* beta2 = (const float*)d_in[16];
    float* out = (float*)d_out;

    float *x1, *bqkv;
    __half *xnh, *xnl, *xn2h, *xn2l, *ath, *atl, *hh, *hl;
    __half *qkvbh, *qkvbl;
    __half *qkvt, *wot, *w1t, *w2t;
    cudaGetSymbolAddress((void**)&x1,    g_x1);
    cudaGetSymbolAddress((void**)&bqkv,  g_bqkv);
    cudaGetSymbolAddress((void**)&xnh,   g_xn_h);
    cudaGetSymbolAddress((void**)&xnl,   g_xn_l);
    cudaGetSymbolAddress((void**)&xn2h,  g_xn2_h);
    cudaGetSymbolAddress((void**)&xn2l,  g_xn2_l);
    cudaGetSymbolAddress((void**)&ath,   g_at_h);
    cudaGetSymbolAddress((void**)&atl,   g_at_l);
    cudaGetSymbolAddress((void**)&hh,    g_h_h);
    cudaGetSymbolAddress((void**)&hl,    g_h_l);
    cudaGetSymbolAddress((void**)&qkvbh, g_qkvb_h);
    cudaGetSymbolAddress((void**)&qkvbl, g_qkvb_l);
    cudaGetSymbolAddress((void**)&qkvt,  g_qkvt);
    cudaGetSymbolAddress((void**)&wot,   g_wot);
    cudaGetSymbolAddress((void**)&w1t,   g_w1t);
    cudaGetSymbolAddress((void**)&w2t,   g_w2t);

    cudaFuncSetAttribute(gemm_mma, cudaFuncAttributeMaxDynamicSharedMemorySize, MSMEM);
    cudaFuncSetAttribute(attn_mma, cudaFuncAttributeMaxDynamicSharedMemorySize, ATTN_SMEM);

    // 1: all weight transposes + fp16 quantize in one launch
    wsplit_all<<<dim3(32, 32, 12), 256>>>(Wq, Wk, Wv, Wo, W1, W2,
                                          qkvt, wot, w1t, w2t);
    // 2
    bias3<<<3*DD/256, 256>>>(bq, bk, bv, bqkv);
    // 3: LN1 -> fp16 split
    ln_split<<<NN, 256>>>(x, g1, beta1, xnh, xnl);

    // 4: fused QKV projection + bias + RoPE; emits fp16 hi/lo q,k,v for attention
    gemm_mma<<<dim3(3*DD/128, NN/128), 256, MSMEM>>>(
        xnh, xnl, qkvt, bqkv, nullptr, nullptr,
        (unsigned short*)qkvbh, (unsigned short*)qkvbl,
        NN, DD, 3*DD, MODE_QKV3);

    __half* qh = qkvbh;
    __half* ql = qkvbl;
    __half* kh = qkvbh + (size_t)NN*DD;
    __half* vh = qkvbh + 2*(size_t)NN*DD;
    __half* vl = qkvbl + 2*(size_t)NN*DD;

    // 5: MMA flash attention (2-product) -> fp16 hi/lo attn output [B,S,D]
    attn_mma<<<dim3(SS/128, BB*HH), 256, ATTN_SMEM>>>(
        qh, ql, kh, vh, vl,
        (unsigned short*)ath, (unsigned short*)atl);

    // 6: x1 = x + attn @ Wo + bo
    gemm_mma<<<dim3(DD/128, NN/128), 256, MSMEM>>>(
        ath, atl, wot, bo, x, x1, nullptr, nullptr,
        NN, DD, DD, MODE_RESID);

    // 7: LN2 -> fp16 split
    ln_split<<<NN, 256>>>(x1, g2, beta2, xn2h, xn2l);

    // 8: FFN up: relu + fp16 split epilogue
    gemm_mma<<<dim3(FF/128, NN/128), 256, MSMEM>>>(
        xn2h, xn2l, w1t, b1, nullptr, nullptr,
        (unsigned short*)hh, (unsigned short*)hl,
        NN, DD, FF, MODE_RELU_SPLIT);

    // 9: FFN down + residual -> out
    gemm_mma<<<dim3(DD/128, NN/128), 256, MSMEM>>>(
        hh, hl, w2t, b2, x1, out, nullptr, nullptr,
        NN, FF, DD, MODE_RESID);
}

// round 15
// speedup vs baseline: 2.3243x; 1.6542x over previous
#include <cuda_runtime.h>
#include <cuda_fp16.h>
#include <math.h>
#include <stdint.h>

#define BB 2
#define SS 2048
#define DD 1024
#define HH 16
#define HD 64
#define FF 4096
#define NN (BB*SS)   // 4096 tokens

// ---------------- scratch (static device globals; no allocs) ----------------
__device__ float g_x1  [NN*DD];      // x + attn_out
__device__ __half g_xn  [NN*DD];     // LN1 out fp16
__device__ __half g_xn2 [NN*DD];     // LN2 out fp16
__device__ __half g_at  [NN*DD];     // attn out [B,S,D] fp16
__device__ __half g_qkvb[3u*NN*DD];  // q,k,v fp16 [t][B,H,S,hd]
__device__ __half g_h   [(size_t)NN*FF];  // FFN hidden fp16
__device__ __half g_qkvt[3*DD*DD];   // weights fp16 [3072,1024]
__device__ __half g_wot [DD*DD];
__device__ __half g_w1t [FF*DD];
__device__ __half g_w2t [DD*FF];
__device__ float g_bqkv[3*DD];

// ---------------- helpers ----------------
__device__ __forceinline__ uint32_t smem_u32(const void* p) {
    return (uint32_t)__cvta_generic_to_shared(p);
}
__device__ __forceinline__ void cp16(uint32_t s, const void* g) {
    asm volatile("cp.async.cg.shared.global [%0], [%1], 16;" :: "r"(s), "l"(g));
}
__device__ __forceinline__ void cp_commit() {
    asm volatile("cp.async.commit_group;" ::: "memory");
}
__device__ __forceinline__ void ldsm4(uint32_t* r, uint32_t addr) {
    asm volatile("ldmatrix.sync.aligned.m8n8.x4.shared.b16 {%0,%1,%2,%3}, [%4];"
        : "=r"(r[0]), "=r"(r[1]), "=r"(r[2]), "=r"(r[3]) : "r"(addr));
}
__device__ __forceinline__ void ldsm4t(uint32_t* r, uint32_t addr) {
    asm volatile("ldmatrix.sync.aligned.m8n8.x4.trans.shared.b16 {%0,%1,%2,%3}, [%4];"
        : "=r"(r[0]), "=r"(r[1]), "=r"(r[2]), "=r"(r[3]) : "r"(addr));
}
__device__ __forceinline__ void mma_f16(float* d, const uint32_t* a, const uint32_t* b) {
    asm volatile("mma.sync.aligned.m16n8k16.row.col.f32.f16.f16.f32 "
        "{%0,%1,%2,%3}, {%4,%5,%6,%7}, {%8,%9}, {%0,%1,%2,%3};"
        : "+f"(d[0]), "+f"(d[1]), "+f"(d[2]), "+f"(d[3])
        : "r"(a[0]), "r"(a[1]), "r"(a[2]), "r"(a[3]), "r"(b[0]), "r"(b[1]));
}
__device__ __forceinline__ uint32_t pack2h(float a, float b) {
    __half ha = __float2half_rn(a), hb = __float2half_rn(b);
    return (uint32_t)__half_as_ushort(ha) | ((uint32_t)__half_as_ushort(hb) << 16);
}
// swizzled offset inside a 64B-wide tile: (row, 16B-chunk c in 0..3)
__device__ __forceinline__ uint32_t tile_off(int r, int c) {
    return (uint32_t)(((r >> 1) * 128) + (((((r & 1) << 2) | c) ^ ((r >> 1) & 7)) << 4));
}

// ---------------- LayerNorm with fp16 output ----------------
__global__ __launch_bounds__(256) void ln_h(const float* __restrict__ x,
                                            const float* __restrict__ gamma,
                                            const float* __restrict__ beta,
                                            __half* __restrict__ o)
{
    int row = blockIdx.x;
    const float4* xr = reinterpret_cast<const float4*>(x + (size_t)row * DD);
    float4 v = xr[threadIdx.x];

    float s  = v.x + v.y + v.z + v.w;
    float sq = v.x*v.x + v.y*v.y + v.z*v.z + v.w*v.w;
    #pragma unroll
    for (int off = 16; off > 0; off >>= 1) {
        s  += __shfl_xor_sync(0xffffffffu, s,  off);
        sq += __shfl_xor_sync(0xffffffffu, sq, off);
    }
    __shared__ float ps[8], psq[8];
    int wid = threadIdx.x >> 5, lane = threadIdx.x & 31;
    if (lane == 0) { ps[wid] = s; psq[wid] = sq; }
    __syncthreads();
    float ts = 0.f, tsq = 0.f;
    #pragma unroll
    for (int i = 0; i < 8; i++) { ts += ps[i]; tsq += psq[i]; }

    float mu   = ts * (1.0f / DD);
    float var  = tsq * (1.0f / DD) - mu * mu;
    float rstd = rsqrtf(var + 1e-5f);

    float4 g = reinterpret_cast<const float4*>(gamma)[threadIdx.x];
    float4 b = reinterpret_cast<const float4*>(beta )[threadIdx.x];
    float o0 = (v.x - mu) * rstd * g.x + b.x;
    float o1 = (v.y - mu) * rstd * g.y + b.y;
    float o2 = (v.z - mu) * rstd * g.z + b.z;
    float o3 = (v.w - mu) * rstd * g.w + b.w;

    uint2 ov = make_uint2(pack2h(o0, o1), pack2h(o2, o3));
    reinterpret_cast<uint2*>(o + (size_t)row*DD)[threadIdx.x] = ov;
}

// ---------------- all-weights transpose + fp16 quantize (single launch) ----------------
__global__ __launch_bounds__(256) void wsplit_all(
    const float* __restrict__ Wq, const float* __restrict__ Wk,
    const float* __restrict__ Wv, const float* __restrict__ Wo,
    const float* __restrict__ W1, const float* __restrict__ W2,
    __half* __restrict__ qkvt, __half* __restrict__ wot,
    __half* __restrict__ w1t,  __half* __restrict__ w2t)
{
    int z = blockIdx.z;
    const float* W;
    __half* Bt;
    int K, N, n0, k0;
    if (z < 4) {
        W  = (z==0) ? Wq : (z==1) ? Wk : (z==2) ? Wv : Wo;
        Bt = (z<3) ? qkvt + (size_t)z*DD*DD : wot;
        K = DD; N = DD;
        n0 = blockIdx.x * 32; k0 = blockIdx.y * 32;
    } else if (z < 8) {
        W = W1; Bt = w1t; K = DD; N = FF;
        n0 = (z-4)*1024 + blockIdx.x * 32; k0 = blockIdx.y * 32;
    } else {
        W = W2; Bt = w2t; K = FF; N = DD;
        n0 = blockIdx.x * 32; k0 = (z-8)*1024 + blockIdx.y * 32;
    }

    __shared__ float t[32][33];
    int tx = threadIdx.x & 31, ty = threadIdx.x >> 5;
    #pragma unroll
    for (int r = 0; r < 4; r++)
        t[ty + 8*r][tx] = W[(size_t)(k0 + ty + 8*r) * N + n0 + tx];
    __syncthreads();
    #pragma unroll
    for (int r = 0; r < 4; r++) {
        int n = ty + 8*r, k = tx;
        Bt[(size_t)(n0 + n) * K + k0 + k] = __float2half_rn(t[k][n]);
    }
}

// ---------------- concat q/k/v biases ----------------
__global__ void bias3(const float* a, const float* b, const float* c, float* o) {
    int i = blockIdx.x * 256 + threadIdx.x;
    o[i] = (i < DD) ? a[i] : (i < 2*DD) ? b[i - DD] : c[i - 2*DD];
}

// ---------------- fp16 1-product warp-MMA GEMM: BK=32, 3-stage, 1 barrier/chunk ----------------
#define MBK 32
#define SOFF_A 0
#define SOFF_B 8192
#define MSTAGE 16384
#define MSMEM (3*MSTAGE)

#define MODE_QKV3  1
#define MODE_RESID 2
#define MODE_RELU  3

__global__ __launch_bounds__(256, 2) void gemm_mma(
    const __half* __restrict__ Av, const __half* __restrict__ Bv,
    const float* __restrict__ bias, const float* __restrict__ resid,
    float* __restrict__ Cf, unsigned short* __restrict__ Ch,
    int M, int K, int N, int mode)
{
    extern __shared__ char smraw[];
    const uint32_t smbase = smem_u32(smraw);

    const int tid  = threadIdx.x;
    const int warp = tid >> 5;
    const int lane = tid & 31;
    const int warpMoff = (warp & 1) * 64;
    const int warpNoff = (warp >> 1) * 32;
    const int mBase = blockIdx.y * 128;
    const int nBase = blockIdx.x * 128;
    const int nk = K / MBK;

    const int g = lane >> 3, l8 = lane & 7;
    uint32_t aoff[2][4], boff[2][2];
    #pragma unroll
    for (int ks = 0; ks < 2; ks++) {
        #pragma unroll
        for (int mt = 0; mt < 4; mt++)
            aoff[ks][mt] = tile_off(warpMoff + mt*16 + (g & 1)*8 + l8, 2*ks + (g >> 1));
        #pragma unroll
        for (int p = 0; p < 2; p++)
            boff[ks][p]  = tile_off(warpNoff + p*16 + (g >> 1)*8 + l8, 2*ks + (g & 1));
    }

    auto load_stage = [&](int chunk, int s) {
        const int k0 = chunk * MBK;
        uint32_t sb = smbase + (uint32_t)s * MSTAGE;
        #pragma unroll
        for (int h = 0; h < 2; h++) {
            int id = tid + h * 256;
            int r = id >> 2, c = id & 3;
            uint32_t so = tile_off(r, c);
            size_t ga = ((size_t)(mBase + r) * K + k0 + c*8) * 2;
            size_t gb = ((size_t)(nBase + r) * K + k0 + c*8) * 2;
            cp16(sb + SOFF_A + so, (const char*)Av + ga);
            cp16(sb + SOFF_B + so, (const char*)Bv + gb);
        }
        cp_commit();
    };

    load_stage(0, 0);
    load_stage(1, 1);

    float acc[4][4][4];
    #pragma unroll
    for (int mt = 0; mt < 4; mt++)
        #pragma unroll
        for (int nt = 0; nt < 4; nt++)
            #pragma unroll
            for (int e = 0; e < 4; e++) acc[mt][nt][e] = 0.f;

    for (int chunk = 0; chunk < nk; chunk++) {
        const int s = chunk % 3;
        if (chunk + 1 < nk) asm volatile("cp.async.wait_group 1;" ::: "memory");
        else                asm volatile("cp.async.wait_group 0;" ::: "memory");
        __syncthreads();
        if (chunk + 2 < nk) load_stage(chunk + 2, (chunk + 2) % 3);

        const uint32_t sb = smbase + (uint32_t)s * MSTAGE;
        #pragma unroll
        for (int ks = 0; ks < 2; ks++) {
            uint32_t bfr[4][2];
            #pragma unroll
            for (int p = 0; p < 2; p++)
                ldsm4(&bfr[2*p][0], sb + SOFF_B + boff[ks][p]);
            #pragma unroll
            for (int mt = 0; mt < 4; mt++) {
                uint32_t af[4];
                ldsm4(af, sb + SOFF_A + aoff[ks][mt]);
                #pragma unroll
                for (int nt = 0; nt < 4; nt++)
                    mma_f16(acc[mt][nt], af, bfr[nt]);
            }
        }
    }

    // ---------------- epilogue ----------------
    const int rl = lane >> 2;
    const int cl = (lane & 3) * 2;

    #pragma unroll
    for (int mt = 0; mt < 4; mt++) {
        #pragma unroll
        for (int nt = 0; nt < 4; nt++) {
            int gr0 = mBase + warpMoff + mt*16 + rl;
            int gc  = nBase + warpNoff + nt*8 + cl;
            float b0 = __ldg(&bias[gc]);
            float b1 = __ldg(&bias[gc + 1]);
            float v00 = acc[mt][nt][0] + b0, v01 = acc[mt][nt][1] + b1;
            float v10 = acc[mt][nt][2] + b0, v11 = acc[mt][nt][3] + b1;

            if (mode == MODE_QKV3) {
                int t = gc >> 10;
                int within = gc & 1023;
                int h = within >> 6, jj = within & 63;
                int p = jj >> 1;
                float inv = expf(-0.28782313663f * (float)p);   // 10000^(-p/32)
                #pragma unroll
                for (int rr = 0; rr < 2; rr++) {
                    int row = gr0 + rr*8;
                    int b = row >> 11, sI = row & 2047;
                    float w0 = rr ? v10 : v00;
                    float w1 = rr ? v11 : v01;
                    if (t < 2) {
                        float sn, cs;
                        sincosf((float)sI * inv, &sn, &cs);
                        float r0 = w0 * cs - w1 * sn;
                        float r1 = w0 * sn + w1 * cs;
                        if (t == 0) { r0 *= 0.125f; r1 *= 0.125f; }
                        w0 = r0; w1 = r1;
                    }
                    size_t ob = (size_t)t * NN * DD +
                                ((size_t)((b*HH + h)*SS + sI)) * HD + jj;
                    reinterpret_cast<uint32_t*>(Ch)[ob >> 1] = pack2h(w0, w1);
                }
            } else if (mode == MODE_RESID) {
                #pragma unroll
                for (int rr = 0; rr < 2; rr++) {
                    int row = gr0 + rr*8;
                    size_t ob = (size_t)row * N + gc;
                    float2 rv = *reinterpret_cast<const float2*>(resid + ob);
                    float2 o = rr ? make_float2(v10 + rv.x, v11 + rv.y)
                                  : make_float2(v00 + rv.x, v01 + rv.y);
                    *reinterpret_cast<float2*>(Cf + ob) = o;
                }
            } else { // MODE_RELU -> fp16
                #pragma unroll
                for (int rr = 0; rr < 2; rr++) {
                    int row = gr0 + rr*8;
                    size_t ob = (size_t)row * N + gc;
                    float w0 = fmaxf(rr ? v10 : v00, 0.f);
                    float w1 = fmaxf(rr ? v11 : v01, 0.f);
                    reinterpret_cast<uint32_t*>(Ch)[ob >> 1] = pack2h(w0, w1);
                }
            }
        }
    }
}

// ---------------- fp16 1-product MMA flash attention ----------------
// S = Q·K^T ; O += P·V.  Q smem 16 KB; stage: K | V (16 KB).
#define AT_SQ    0
#define AT_STAGE 16384
#define AT_SSZ   16384
#define AT_K     0
#define AT_V     8192
#define ATTN_SMEM (16384 + 2*16384)

__global__ __launch_bounds__(256, 2) void attn_mma(
    const __half* __restrict__ Q, const __half* __restrict__ K,
    const __half* __restrict__ V,
    unsigned short* __restrict__ O)
{
    extern __shared__ char smraw[];
    const uint32_t sm = smem_u32(smraw);
    const int tid = threadIdx.x, warp = tid >> 5, lane = tid & 31;
    const int bh = blockIdx.y;
    const int q0 = blockIdx.x * 128;
    const int g = lane >> 3, l8 = lane & 7;
    const int rl = lane >> 2, cl = (lane & 3) * 2;

    // load Q tile (part of first commit group)
    #pragma unroll
    for (int t = 0; t < 4; t++) {
        int w = t * 256 + tid;               // 0..1023
        int r = w >> 3, c = w & 7;
        uint32_t off = AT_SQ + (c >> 2) * 8192 + tile_off(r, c & 3);
        const char* gp = (const char*)Q +
                         ((size_t)((size_t)bh * SS + q0 + r) * HD + c * 8) * 2;
        cp16(sm + off, gp);
    }

    auto load_kv = [&](int kb, int s) {
        uint32_t sb = sm + AT_STAGE + (uint32_t)s * AT_SSZ;
        #pragma unroll
        for (int t = 0; t < 4; t++) {
            int buf = t >> 1;                // 0=K 1=V
            int w = (t & 1) * 256 + tid;     // 0..511
            int r = w >> 3, c = w & 7;
            uint32_t off = (uint32_t)buf * 8192 + (c >> 2) * 4096 + tile_off(r, c & 3);
            const __half* src = (buf == 0) ? K : V;
            const char* gp = (const char*)src + ((size_t)((size_t)bh * SS + kb + r) * HD + c * 8) * 2;
            cp16(sb + off, gp);
        }
        cp_commit();
    };

    load_kv(0, 0);
    load_kv(64, 1);

    float m0 = -1e30f, m1 = -1e30f, l0 = 0.f, l1 = 0.f;
    float acc[8][4];
    #pragma unroll
    for (int nt = 0; nt < 8; nt++)
        #pragma unroll
        for (int e = 0; e < 4; e++) acc[nt][e] = 0.f;

    const int NT = SS / 64;
    for (int it = 0; it < NT; it++) {
        if (it + 1 < NT) asm volatile("cp.async.wait_group 1;" ::: "memory");
        else             asm volatile("cp.async.wait_group 0;" ::: "memory");
        __syncthreads();
        const uint32_t sb = sm + AT_STAGE + (uint32_t)(it & 1) * AT_SSZ;

        // ---- S = Q K^T ----
        float sacc[8][4];
        #pragma unroll
        for (int nt = 0; nt < 8; nt++)
            #pragma unroll
            for (int e = 0; e < 4; e++) sacc[nt][e] = 0.f;

        #pragma unroll
        for (int ks = 0; ks < 4; ks++) {
            uint32_t qoff = AT_SQ + (uint32_t)((ks >> 1) * 8192) +
                            tile_off(warp*16 + (g & 1)*8 + l8, 2*(ks & 1) + (g >> 1));
            uint32_t qf[4];
            ldsm4(qf, sm + qoff);
            #pragma unroll
            for (int p = 0; p < 4; p++) {
                uint32_t kf[4];
                uint32_t ko = (uint32_t)((ks >> 1) * 4096) +
                              tile_off(p*16 + (g >> 1)*8 + l8, 2*(ks & 1) + (g & 1));
                ldsm4(kf, sb + AT_K + ko);
                mma_f16(sacc[2*p + 0], qf, &kf[0]);
                mma_f16(sacc[2*p + 1], qf, &kf[2]);
            }
        }

        // ---- online softmax ----
        float mx0 = -1e30f, mx1 = -1e30f;
        #pragma unroll
        for (int nt = 0; nt < 8; nt++) {
            mx0 = fmaxf(mx0, fmaxf(sacc[nt][0], sacc[nt][1]));
            mx1 = fmaxf(mx1, fmaxf(sacc[nt][2], sacc[nt][3]));
        }
        mx0 = fmaxf(mx0, __shfl_xor_sync(0xffffffffu, mx0, 1));
        mx0 = fmaxf(mx0, __shfl_xor_sync(0xffffffffu, mx0, 2));
        mx1 = fmaxf(mx1, __shfl_xor_sync(0xffffffffu, mx1, 1));
        mx1 = fmaxf(mx1, __shfl_xor_sync(0xffffffffu, mx1, 2));

        float mn0 = fmaxf(m0, mx0), mn1 = fmaxf(m1, mx1);
        float a0 = __expf(m0 - mn0), a1 = __expf(m1 - mn1);
        float rs0 = 0.f, rs1 = 0.f;
        #pragma unroll
        for (int nt = 0; nt < 8; nt++) {
            sacc[nt][0] = __expf(sacc[nt][0] - mn0);
            sacc[nt][1] = __expf(sacc[nt][1] - mn0);
            sacc[nt][2] = __expf(sacc[nt][2] - mn1);
            sacc[nt][3] = __expf(sacc[nt][3] - mn1);
            rs0 += sacc[nt][0] + sacc[nt][1];
            rs1 += sacc[nt][2] + sacc[nt][3];
        }
        rs0 += __shfl_xor_sync(0xffffffffu, rs0, 1);
        rs0 += __shfl_xor_sync(0xffffffffu, rs0, 2);
        rs1 += __shfl_xor_sync(0xffffffffu, rs1, 1);
        rs1 += __shfl_xor_sync(0xffffffffu, rs1, 2);
        l0 = l0 * a0 + rs0;  m0 = mn0;
        l1 = l1 * a1 + rs1;  m1 = mn1;
        #pragma unroll
        for (int nt = 0; nt < 8; nt++) {
            acc[nt][0] *= a0; acc[nt][1] *= a0;
            acc[nt][2] *= a1; acc[nt][3] *= a1;
        }

        // ---- O += P V ; V row-major, trans ldmatrix ----
        #pragma unroll
        for (int ks = 0; ks < 4; ks++) {
            uint32_t aP[4];
            #pragma unroll
            for (int half = 0; half < 2; half++) {
                int nt = 2*ks + half;
                aP[half*2 + 0] = pack2h(sacc[nt][0], sacc[nt][1]);
                aP[half*2 + 1] = pack2h(sacc[nt][2], sacc[nt][3]);
            }
            int vrow = 16*ks + (g & 1)*8 + l8;
            #pragma unroll
            for (int p = 0; p < 4; p++) {
                uint32_t vf[4];
                int c = p*2 + (g >> 1);            // 16B d-chunk 0..7
                uint32_t vo = (uint32_t)((c >> 2) * 4096) + tile_off(vrow, c & 3);
                ldsm4t(vf, sb + AT_V + vo);
                mma_f16(acc[2*p + 0], aP, &vf[0]);
                mma_f16(acc[2*p + 1], aP, &vf[2]);
            }
        }

        __syncthreads();
        if (it + 2 < NT) load_kv((it + 2) * 64, it & 1);
    }

    // ---- epilogue: normalize, fp16, write [B,S,D] ----
    float i0 = 1.f / l0, i1 = 1.f / l1;
    int b = bh >> 4, h = bh & 15;
    int s0r = q0 + warp * 16 + rl;
    #pragma unroll
    for (int nt = 0; nt < 8; nt++) {
        int col = h * 64 + nt * 8 + cl;
        {
            size_t ob = (size_t)(b * SS + s0r) * DD + col;
            reinterpret_cast<uint32_t*>(O)[ob >> 1] = pack2h(acc[nt][0] * i0, acc[nt][1] * i0);
        }
        {
            size_t ob = (size_t)(b * SS + s0r + 8) * DD + col;
            reinterpret_cast<uint32_t*>(O)[ob >> 1] = pack2h(acc[nt][2] * i1, acc[nt][3] * i1);
        }
    }
}

// ---------------- host launch ----------------
extern "C" void kernel_launch(void* const* d_in, const int* in_sizes, int n_in,
                              void* d_out, int out_size)
{
    const float* x     = (const float*)d_in[0];
    const float* Wq    = (const float*)d_in[1];
    const float* bq    = (const float*)d_in[2];
    const float* Wk    = (const float*)d_in[3];
    const float* bk    = (const float*)d_in[4];
    const float* Wv    = (const float*)d_in[5];
    const float* bv    = (const float*)d_in[6];
    const float* Wo    = (const float*)d_in[7];
    const float* bo    = (const float*)d_in[8];
    const float* W1    = (const float*)d_in[9];
    const float* b1    = (const float*)d_in[10];
    const float* W2    = (const float*)d_in[11];
    const float* b2    = (const float*)d_in[12];
    const float* g1    = (const float*)d_in[13];
    const float* beta1 = (const float*)d_in[14];
    const float* g2    = (const float*)d_in[15];
    const float* beta2 = (const float*)d_in[16];
    float* out = (float*)d_out;

    float *x1, *bqkv;
    __half *xn, *xn2, *at, *hbuf, *qkvb;
    __half *qkvt, *wot, *w1t, *w2t;
    cudaGetSymbolAddress((void**)&x1,   g_x1);
    cudaGetSymbolAddress((void**)&bqkv, g_bqkv);
    cudaGetSymbolAddress((void**)&xn,   g_xn);
    cudaGetSymbolAddress((void**)&xn2,  g_xn2);
    cudaGetSymbolAddress((void**)&at,   g_at);
    cudaGetSymbolAddress((void**)&hbuf, g_h);
    cudaGetSymbolAddress((void**)&qkvb, g_qkvb);
    cudaGetSymbolAddress((void**)&qkvt, g_qkvt);
    cudaGetSymbolAddress((void**)&wot,  g_wot);
    cudaGetSymbolAddress((void**)&w1t,  g_w1t);
    cudaGetSymbolAddress((void**)&w2t,  g_w2t);

    cudaFuncSetAttribute(gemm_mma, cudaFuncAttributeMaxDynamicSharedMemorySize, MSMEM);
    cudaFuncSetAttribute(attn_mma, cudaFuncAttributeMaxDynamicSharedMemorySize, ATTN_SMEM);

    // 1: all weight transposes + fp16 quantize in one launch
    wsplit_all<<<dim3(32, 32, 12), 256>>>(Wq, Wk, Wv, Wo, W1, W2,
                                          qkvt, wot, w1t, w2t);
    // 2
    bias3<<<3*DD/256, 256>>>(bq, bk, bv, bqkv);
    // 3: LN1 -> fp16
    ln_h<<<NN, 256>>>(x, g1, beta1, xn);

    // 4: fused QKV projection + bias + RoPE; emits fp16 q,k,v
    gemm_mma<<<dim3(3*DD/128, NN/128), 256, MSMEM>>>(
        xn, qkvt, bqkv, nullptr, nullptr, (unsigned short*)qkvb,
        NN, DD, 3*DD, MODE_QKV3);

    __half* q = qkvb;
    __half* k = qkvb + (size_t)NN*DD;
    __half* v = qkvb + 2*(size_t)NN*DD;

    // 5: MMA flash attention (1-product) -> fp16 attn output [B,S,D]
    attn_mma<<<dim3(SS/128, BB*HH), 256, ATTN_SMEM>>>(
        q, k, v, (unsigned short*)at);

    // 6: x1 = x + attn @ Wo + bo
    gemm_mma<<<dim3(DD/128, NN/128), 256, MSMEM>>>(
        at, wot, bo, x, x1, nullptr,
        NN, DD, DD, MODE_RESID);

    // 7: LN2 -> fp16
    ln_h<<<NN, 256>>>(x1, g2, beta2, xn2);

    // 8: FFN up: relu -> fp16
    gemm_mma<<<dim3(FF/128, NN/128), 256, MSMEM>>>(
        xn2, w1t, b1, nullptr, nullptr, (unsigned short*)hbuf,
        NN, DD, FF, MODE_RELU);

    // 9: FFN down + residual -> out
    gemm_mma<<<dim3(DD/128, NN/128), 256, MSMEM>>>(
        hbuf, w2t, b2, x1, out, nullptr,
        NN, FF, DD, MODE_RESID);
}